// round 9
// baseline (speedup 1.0000x reference)
#include <cuda_runtime.h>
#include <cuda_fp16.h>
#include <cstdint>

// ---------------------------------------------------------------------------
// Cross-modal attention, aq=1, softmax=1, sigmoid=0.
// B=16, N=4096, Kq=64, C=1024, H=8, d=128. Output (16,64,1024) fp32.
//
//   1) q    = aud @ Wq^T                  (1024 x 1024 x 1024)  NT   [fp16 mma]
//   2) qt_bh = Q_bh @ Wk_h                (64 x 1024 x 128) x128 NN  [fp32]
//   3) sc_b  = qt_b @ img_b^T * scale     (512 x 4096 x 1024) x16 NT [fp16 mma]
//   4) softmax rows of sc (8192 rows x 4096)
//   5) t_b   = sc_b @ img_b               (512 x 1024 x 4096) x16 NN [fp16 mma]
//   6) out_bh = t_bh @ Wv_h^T             (64 x 128 x 1024) x128 NT  [fp32]
//
// R9: fp16 m16n8k16 mma (2x FLOP/instr vs tf32 k8; same 11-bit significand),
//     BK=64, all fragments via ldmatrix (incl. B-NN via ldmatrix.trans).
// ---------------------------------------------------------------------------

__device__ __align__(16) float g_q[16 * 64 * 1024];        //   4 MB
__device__ __align__(16) float g_qt[16 * 8 * 64 * 1024];   //  32 MB
__device__ __align__(16) float g_sc[16 * 512 * 4096];      // 128 MB
__device__ __align__(16) float g_t[16 * 8 * 64 * 1024];    //  32 MB

__device__ __forceinline__ void ldsm_x4(uint32_t& r0, uint32_t& r1,
                                        uint32_t& r2, uint32_t& r3,
                                        uint32_t addr) {
    asm volatile(
        "ldmatrix.sync.aligned.m8n8.x4.shared.b16 {%0,%1,%2,%3}, [%4];"
        : "=r"(r0), "=r"(r1), "=r"(r2), "=r"(r3) : "r"(addr));
}

__device__ __forceinline__ void ldsm_x4_t(uint32_t& r0, uint32_t& r1,
                                          uint32_t& r2, uint32_t& r3,
                                          uint32_t addr) {
    asm volatile(
        "ldmatrix.sync.aligned.m8n8.x4.trans.shared.b16 {%0,%1,%2,%3}, [%4];"
        : "=r"(r0), "=r"(r1), "=r"(r2), "=r"(r3) : "r"(addr));
}

__device__ __forceinline__ uint32_t h2bits(__half2 h) {
    return *reinterpret_cast<uint32_t*>(&h);
}

// ======================= FP16 tensor-core GEMM =============================
// C[M,N] = alpha * A[M,K] * op(B), fp32 inputs converted to fp16 in smem,
// fp32 accumulate. TRANSB: B is N x K row-major (NT). else K x N (NN).
// Block tile 128x128x64, 8 warps (4x2), warp tile 32x64, mma m16n8k16.
template <bool TRANSB>
__global__ __launch_bounds__(256)
void h16_gemm_kernel(const float* __restrict__ Ag, const float* __restrict__ Bg,
                     float* __restrict__ Cg,
                     int K, int lda, int ldb, int ldc,
                     long aOff1, long bOff1, long cOff1, float alpha) {
    const float* A = Ag + (long)blockIdx.z * aOff1;
    const float* B = Bg + (long)blockIdx.z * bOff1;
    float* C = Cg + (long)blockIdx.z * cOff1;

    constexpr int AS_STRIDE = 72;      // 64 + 8 halves: 144B rows, 16B aligned
    constexpr int BS_STRIDE_NT = 72;
    constexpr int BS_STRIDE_NN = 136;  // 128 + 8 halves: 272B rows

    __shared__ __align__(16) __half As[128 * AS_STRIDE];
    __shared__ __align__(16) __half Bs[TRANSB ? 128 * BS_STRIDE_NT
                                              : 64 * BS_STRIDE_NN];

    const int tid = threadIdx.x;
    const int lane = tid & 31;
    const int warp = tid >> 5;
    const int g = lane >> 2;
    const int tg = lane & 3;
    const int wm = warp >> 1;     // 0..3 -> warp row * 32
    const int wn = warp & 1;      // 0..1 -> warp col * 64
    const int m0 = blockIdx.y * 128;
    const int n0 = blockIdx.x * 128;

    // ldmatrix per-lane addressing
    const int r8 = lane & 7;
    const int quad = lane >> 3;
    // A x4 tiles: (r+0,k+0),(r+8,k+0),(r+0,k+8),(r+8,k+8) -> a0..a3
    const int a_row = wm * 32 + ((quad & 1) << 3) + r8;
    const int a_k = (quad >> 1) << 3;
    const uint32_t a_base0 =
        (uint32_t)__cvta_generic_to_shared(&As[a_row * AS_STRIDE + a_k]);
    const uint32_t a_base1 = a_base0 + 16 * AS_STRIDE * 2;
    // B addressing
    uint32_t b_base;
    if constexpr (TRANSB) {
        // tiles: (n+0,k+0),(n+0,k+8),(n+8,k+0),(n+8,k+8) -> b0/b1 of ni, ni+1
        const int b_row = wn * 64 + ((quad >> 1) << 3) + r8;
        const int b_k = (quad & 1) << 3;
        b_base = (uint32_t)__cvta_generic_to_shared(
            &Bs[b_row * BS_STRIDE_NT + b_k]);
    } else {
        // trans tiles: (k+0,n+0),(k+8,n+0),(k+0,n+8),(k+8,n+8)
        const int b_krow = ((quad & 1) << 3) + r8;
        const int b_n = wn * 64 + ((quad >> 1) << 3);
        b_base = (uint32_t)__cvta_generic_to_shared(
            &Bs[b_krow * BS_STRIDE_NN + b_n]);
    }

    // loader coordinates (BK=64)
    const int arow = tid >> 4;        // 0..15 -> rows arow + 16*i? no: idx>>4
    const int acol = (tid & 15) * 4;
    const int brow_nn = tid >> 5;
    const int bcol_nn = (tid & 31) * 4;

    float acc[2][8][4] = {};

    for (int kt = 0; kt < K; kt += 64) {
        // ---- A tile 128x64 -> As[m][k] fp16 ----
        #pragma unroll
        for (int i = 0; i < 8; i++) {
            int idx = tid + i * 256;
            int row = idx >> 4;           // 0..127
            int c = (idx & 15) * 4;       // 0..60
            float4 v = *reinterpret_cast<const float4*>(
                A + (long)(m0 + row) * lda + kt + c);
            __half2 h0 = __floats2half2_rn(v.x, v.y);
            __half2 h1 = __floats2half2_rn(v.z, v.w);
            uint2 u = {h2bits(h0), h2bits(h1)};
            *reinterpret_cast<uint2*>(&As[row * AS_STRIDE + c]) = u;
        }
        // ---- B tile ----
        if constexpr (TRANSB) {
            #pragma unroll
            for (int i = 0; i < 8; i++) {
                int idx = tid + i * 256;
                int row = idx >> 4;
                int c = (idx & 15) * 4;
                float4 v = *reinterpret_cast<const float4*>(
                    B + (long)(n0 + row) * ldb + kt + c);
                __half2 h0 = __floats2half2_rn(v.x, v.y);
                __half2 h1 = __floats2half2_rn(v.z, v.w);
                uint2 u = {h2bits(h0), h2bits(h1)};
                *reinterpret_cast<uint2*>(&Bs[row * BS_STRIDE_NT + c]) = u;
            }
        } else {
            #pragma unroll
            for (int i = 0; i < 8; i++) {
                int idx = tid + i * 256;
                int row = idx >> 5;           // k: 0..63
                int c = (idx & 31) * 4;       // n: 0..124
                float4 v = *reinterpret_cast<const float4*>(
                    B + (long)(kt + row) * ldb + n0 + c);
                __half2 h0 = __floats2half2_rn(v.x, v.y);
                __half2 h1 = __floats2half2_rn(v.z, v.w);
                uint2 u = {h2bits(h0), h2bits(h1)};
                *reinterpret_cast<uint2*>(&Bs[row * BS_STRIDE_NN + c]) = u;
            }
        }
        __syncthreads();

        #pragma unroll
        for (int ks = 0; ks < 4; ks++) {   // 4 x k16
            const uint32_t koff = (uint32_t)ks * 16 * 2;  // bytes along k

            uint32_t af[2][4];
            ldsm_x4(af[0][0], af[0][1], af[0][2], af[0][3], a_base0 + koff);
            ldsm_x4(af[1][0], af[1][1], af[1][2], af[1][3], a_base1 + koff);

            uint32_t bf[8][2];
            if constexpr (TRANSB) {
                #pragma unroll
                for (int nip = 0; nip < 4; nip++) {
                    ldsm_x4(bf[2 * nip][0], bf[2 * nip][1],
                            bf[2 * nip + 1][0], bf[2 * nip + 1][1],
                            b_base + nip * (16 * BS_STRIDE_NT * 2) + koff);
                }
            } else {
                const uint32_t krow_off = (uint32_t)ks * 16 * BS_STRIDE_NN * 2;
                #pragma unroll
                for (int nip = 0; nip < 4; nip++) {
                    ldsm_x4_t(bf[2 * nip][0], bf[2 * nip][1],
                              bf[2 * nip + 1][0], bf[2 * nip + 1][1],
                              b_base + krow_off + nip * (16 * 2));
                }
            }

            #pragma unroll
            for (int mi = 0; mi < 2; mi++)
                #pragma unroll
                for (int ni = 0; ni < 8; ni++) {
                    float* c = acc[mi][ni];
                    asm volatile(
                        "mma.sync.aligned.m16n8k16.row.col.f32.f16.f16.f32 "
                        "{%0,%1,%2,%3}, {%4,%5,%6,%7}, {%8,%9}, {%0,%1,%2,%3};"
                        : "+f"(c[0]), "+f"(c[1]), "+f"(c[2]), "+f"(c[3])
                        : "r"(af[mi][0]), "r"(af[mi][1]), "r"(af[mi][2]),
                          "r"(af[mi][3]), "r"(bf[ni][0]), "r"(bf[ni][1]));
                }
        }
        __syncthreads();
    }

    // ---- epilogue ----
    #pragma unroll
    for (int mi = 0; mi < 2; mi++) {
        int r0 = m0 + wm * 32 + mi * 16 + g;
        #pragma unroll
        for (int ni = 0; ni < 8; ni++) {
            int col = n0 + wn * 64 + ni * 8 + tg * 2;
            float2 v0 = {alpha * acc[mi][ni][0], alpha * acc[mi][ni][1]};
            float2 v1 = {alpha * acc[mi][ni][2], alpha * acc[mi][ni][3]};
            *reinterpret_cast<float2*>(C + (long)r0 * ldc + col) = v0;
            *reinterpret_cast<float2*>(C + (long)(r0 + 8) * ldc + col) = v1;
        }
    }
}

// ======================= fp32 SGEMM (small steps) ==========================
template <int BM, int BN, int BK, int TM, int TN, bool TRANSB>
__global__ __launch_bounds__((BM / TM) * (BN / TN))
void sgemm_kernel(const float* __restrict__ Ag, const float* __restrict__ Bg,
                  float* __restrict__ Cg,
                  int M, int N, int K, int lda, int ldb, int ldc,
                  long aOff1, long aOff2, long bOff1, long bOff2,
                  long cOff1, long cOff2, int Z2, float alpha) {
    constexpr int THREADS = (BM / TM) * (BN / TN);
    const int z = blockIdx.z;
    const int z1 = z / Z2;
    const int z2 = z - z1 * Z2;
    const float* A = Ag + (long)z1 * aOff1 + (long)z2 * aOff2;
    const float* B = Bg + (long)z1 * bOff1 + (long)z2 * bOff2;
    float* C = Cg + (long)z1 * cOff1 + (long)z2 * cOff2;

    __shared__ __align__(16) float As[BK][BM];
    __shared__ __align__(16) float Bs[BK][BN];

    const int tid = threadIdx.x;
    const int m0 = blockIdx.y * BM;
    const int n0 = blockIdx.x * BN;
    const int tm0 = (tid / (BN / TN)) * TM;
    const int tn0 = (tid % (BN / TN)) * TN;

    float acc[TM][TN] = {};

    constexpr int KV = BK / 4;
    constexpr int A_PER = (BM * KV) / THREADS;

    for (int kt = 0; kt < K; kt += BK) {
        #pragma unroll
        for (int i = 0; i < A_PER; i++) {
            int idx = tid + i * THREADS;
            int row = idx / KV;
            int cv = idx - row * KV;
            float4 v = *reinterpret_cast<const float4*>(
                A + (long)(m0 + row) * lda + kt + cv * 4);
            As[cv * 4 + 0][row] = v.x;
            As[cv * 4 + 1][row] = v.y;
            As[cv * 4 + 2][row] = v.z;
            As[cv * 4 + 3][row] = v.w;
        }
        if constexpr (TRANSB) {
            constexpr int B_PER = (BN * KV) / THREADS;
            #pragma unroll
            for (int i = 0; i < B_PER; i++) {
                int idx = tid + i * THREADS;
                int row = idx / KV;
                int cv = idx - row * KV;
                float4 v = *reinterpret_cast<const float4*>(
                    B + (long)(n0 + row) * ldb + kt + cv * 4);
                Bs[cv * 4 + 0][row] = v.x;
                Bs[cv * 4 + 1][row] = v.y;
                Bs[cv * 4 + 2][row] = v.z;
                Bs[cv * 4 + 3][row] = v.w;
            }
        } else {
            constexpr int NV = BN / 4;
            constexpr int B_PER = (BK * NV) / THREADS;
            #pragma unroll
            for (int i = 0; i < B_PER; i++) {
                int idx = tid + i * THREADS;
                int row = idx / NV;
                int cv = idx - row * NV;
                float4 v = *reinterpret_cast<const float4*>(
                    B + (long)(kt + row) * ldb + n0 + cv * 4);
                *reinterpret_cast<float4*>(&Bs[row][cv * 4]) = v;
            }
        }
        __syncthreads();

        #pragma unroll
        for (int kk = 0; kk < BK; kk++) {
            float ra[TM], rb[TN];
            #pragma unroll
            for (int i = 0; i < TM / 4; i++)
                *reinterpret_cast<float4*>(&ra[i * 4]) =
                    *reinterpret_cast<const float4*>(&As[kk][tm0 + i * 4]);
            #pragma unroll
            for (int j = 0; j < TN / 4; j++)
                *reinterpret_cast<float4*>(&rb[j * 4]) =
                    *reinterpret_cast<const float4*>(&Bs[kk][tn0 + j * 4]);
            #pragma unroll
            for (int i = 0; i < TM; i++)
                #pragma unroll
                for (int j = 0; j < TN; j++)
                    acc[i][j] = fmaf(ra[i], rb[j], acc[i][j]);
        }
        __syncthreads();
    }

    #pragma unroll
    for (int i = 0; i < TM; i++) {
        #pragma unroll
        for (int j = 0; j < TN / 4; j++) {
            float4 v;
            v.x = alpha * acc[i][j * 4 + 0];
            v.y = alpha * acc[i][j * 4 + 1];
            v.z = alpha * acc[i][j * 4 + 2];
            v.w = alpha * acc[i][j * 4 + 3];
            *reinterpret_cast<float4*>(
                C + (long)(m0 + tm0 + i) * ldc + n0 + tn0 + j * 4) = v;
        }
    }
}

// ======================= softmax ===========================================
__global__ __launch_bounds__(256) void softmax4096_kernel(float* __restrict__ S) {
    float* row = S + (size_t)blockIdx.x * 4096;
    const int tid = threadIdx.x;
    __shared__ float red[8];

    float4 v[4];
    float maxv = -3.4e38f;
    #pragma unroll
    for (int i = 0; i < 4; i++) {
        v[i] = reinterpret_cast<const float4*>(row)[tid + i * 256];
        maxv = fmaxf(maxv, fmaxf(fmaxf(v[i].x, v[i].y), fmaxf(v[i].z, v[i].w)));
    }
    #pragma unroll
    for (int o = 16; o > 0; o >>= 1)
        maxv = fmaxf(maxv, __shfl_xor_sync(0xffffffffu, maxv, o));
    if ((tid & 31) == 0) red[tid >> 5] = maxv;
    __syncthreads();
    float bm = red[0];
    #pragma unroll
    for (int i = 1; i < 8; i++) bm = fmaxf(bm, red[i]);

    float sum = 0.f;
    #pragma unroll
    for (int i = 0; i < 4; i++) {
        v[i].x = __expf(v[i].x - bm);
        v[i].y = __expf(v[i].y - bm);
        v[i].z = __expf(v[i].z - bm);
        v[i].w = __expf(v[i].w - bm);
        sum += (v[i].x + v[i].y) + (v[i].z + v[i].w);
    }
    __syncthreads();
    #pragma unroll
    for (int o = 16; o > 0; o >>= 1) sum += __shfl_xor_sync(0xffffffffu, sum, o);
    if ((tid & 31) == 0) red[tid >> 5] = sum;
    __syncthreads();
    float tot = 0.f;
    #pragma unroll
    for (int i = 0; i < 8; i++) tot += red[i];
    const float inv = 1.0f / tot;
    #pragma unroll
    for (int i = 0; i < 4; i++) {
        v[i].x *= inv; v[i].y *= inv; v[i].z *= inv; v[i].w *= inv;
        reinterpret_cast<float4*>(row)[tid + i * 256] = v[i];
    }
}

extern "C" void kernel_launch(void* const* d_in, const int* in_sizes, int n_in,
                              void* d_out, int out_size) {
    const float* img = (const float*)d_in[0];  // (16,4096,1024)
    const float* aud = (const float*)d_in[1];  // (16,64,1024)
    const float* Wq = (const float*)d_in[2];   // (1024,1024)
    const float* Wk = (const float*)d_in[3];
    const float* Wv = (const float*)d_in[4];
    float* out = (float*)d_out;                // (16,64,1024)

    float *q, *qt, *sc, *t;
    cudaGetSymbolAddress((void**)&q, g_q);
    cudaGetSymbolAddress((void**)&qt, g_qt);
    cudaGetSymbolAddress((void**)&sc, g_sc);
    cudaGetSymbolAddress((void**)&t, g_t);

    const float scale = 0.08838834764831845f;  // (1024/8)^-0.5

    // 1) q = aud @ Wq^T : M=1024, N=1024, K=1024  (fp16, NT)
    h16_gemm_kernel<true><<<dim3(8, 8, 1), 256>>>(
        aud, Wq, q, 1024, 1024, 1024, 1024, 0, 0, 0, 1.0f);

    // 2) qt[b,h] = Q_bh @ Wk_h : M=64, N=1024, K=128, z = b*8+h (fp32, NN)
    sgemm_kernel<64, 64, 16, 4, 4, false><<<dim3(16, 1, 128), 256>>>(
        q, Wk, qt, 64, 1024, 128, 1024, 1024, 1024,
        65536, 128, 0, 131072, 524288, 65536, 8, 1.0f);

    // 3) sc_b = qt_b @ img_b^T * scale : M=512, N=4096, K=1024 (fp16, NT)
    h16_gemm_kernel<true><<<dim3(32, 4, 16), 256>>>(
        qt, img, sc, 1024, 1024, 1024, 4096,
        524288, 4194304, 2097152, scale);

    // 4) softmax over the 4096-wide rows (16*512 rows)
    softmax4096_kernel<<<16 * 512, 256>>>(sc);

    // 5) t_b = P_b @ img_b : M=512, N=1024, K=4096 (fp16, NN)
    h16_gemm_kernel<false><<<dim3(8, 4, 16), 256>>>(
        sc, img, t, 4096, 4096, 1024, 1024,
        2097152, 4194304, 524288, 1.0f);

    // 6) out[b,:,h*128:(h+1)*128] = t_bh @ Wv_h^T : M=64, N=128, K=1024 (fp32, NT)
    sgemm_kernel<64, 64, 16, 4, 4, true><<<dim3(2, 1, 128), 256>>>(
        t, Wv, out, 64, 128, 1024, 1024, 1024, 1024,
        524288, 65536, 0, 131072, 65536, 128, 8, 1.0f);
}

// round 11
// speedup vs baseline: 1.5779x; 1.5779x over previous
#include <cuda_runtime.h>
#include <cuda_fp16.h>
#include <cstdint>

// ---------------------------------------------------------------------------
// Cross-modal attention, aq=1, softmax=1, sigmoid=0.
// B=16, N=4096, Kq=64, C=1024, H=8, d=128. Output (16,64,1024) fp32.
//
//   0) prep: img_h = fp16(img); img_ht = fp16(img^T per batch)
//   1) q    = aud @ Wq^T          (1024x1024x1024) NT  [tf32 mma] -> fp32
//   2) qt_h = Q_bh @ Wk_h         (64x1024x128)x128 NN [fp32]     -> fp16
//   3) sc_b = qt_b @ img_b^T * s  (512x4096x1024)x16  [fp16 mma NT, fp16 in]
//   4) softmax rows (fp32 -> fp16)
//   5) t_b  = sc_b @ img_b        (512x1024x4096)x16  [fp16 mma NT via img^T]
//   6) out  = t_bh @ Wv_h^T       (64x128x1024)x128 NT [fp32]
//
// R11: all big-GEMM operands pre-staged in fp16 -> gmem/L2 traffic halved,
//      mainloop loaders are pure uint4 copies (no cvt).
// ---------------------------------------------------------------------------

__device__ __align__(16) float  g_q[16 * 64 * 1024];          //   4 MB
__device__ __align__(16) __half g_qth[16 * 8 * 64 * 1024];    //  16 MB
__device__ __align__(16) float  g_sc[16 * 512 * 4096];        // 128 MB
__device__ __align__(16) __half g_sch[16 * 512 * 4096];       //  64 MB
__device__ __align__(16) __half g_imgh[16 * 4096 * 1024];     // 128 MB
__device__ __align__(16) __half g_imght[16 * 1024 * 4096];    // 128 MB
__device__ __align__(16) float  g_t[16 * 8 * 64 * 1024];      //  32 MB

__device__ __forceinline__ uint32_t f2tf32(float x) {
    uint32_t r;
    asm("cvt.rna.tf32.f32 %0, %1;" : "=r"(r) : "f"(x));
    return r;
}
__device__ __forceinline__ void ldsm_x4(uint32_t& r0, uint32_t& r1,
                                        uint32_t& r2, uint32_t& r3,
                                        uint32_t addr) {
    asm volatile(
        "ldmatrix.sync.aligned.m8n8.x4.shared.b16 {%0,%1,%2,%3}, [%4];"
        : "=r"(r0), "=r"(r1), "=r"(r2), "=r"(r3) : "r"(addr));
}
__device__ __forceinline__ uint32_t h2bits(__half2 h) {
    return *reinterpret_cast<uint32_t*>(&h);
}

// ======================= FP16-input NT tensor GEMM =========================
// C[M,N] = alpha * A[M,K] * B[N,K]^T, A/B fp16 row-major (K contiguous),
// fp32 accumulate. Block tile 128x128x64, 8 warps (4x2), warp 32x64, k16 mma.
__global__ __launch_bounds__(256)
void h16_gemm_nt_kernel(const __half* __restrict__ Ag,
                        const __half* __restrict__ Bg,
                        float* __restrict__ Cg,
                        int K, int lda, int ldb, int ldc,
                        long aOff, long bOff, long cOff, float alpha) {
    const __half* A = Ag + (long)blockIdx.z * aOff;
    const __half* B = Bg + (long)blockIdx.z * bOff;
    float* C = Cg + (long)blockIdx.z * cOff;

    constexpr int ST = 72;  // 64 + 8 halves; 144B row pitch (9 granules, cf-free)
    __shared__ __align__(16) __half As[128 * ST];
    __shared__ __align__(16) __half Bs[128 * ST];

    const int tid = threadIdx.x;
    const int lane = tid & 31;
    const int warp = tid >> 5;
    const int g = lane >> 2;
    const int tg = lane & 3;
    const int wm = warp >> 1;     // 0..3 -> warp row * 32
    const int wn = warp & 1;      // 0..1 -> warp col * 64
    const int m0 = blockIdx.y * 128;
    const int n0 = blockIdx.x * 128;

    // ldmatrix per-lane addressing (validated in R9)
    const int r8 = lane & 7;
    const int quad = lane >> 3;
    // A tiles: (r+0,k+0),(r+8,k+0),(r+0,k+8),(r+8,k+8) -> a0..a3
    const int a_row = wm * 32 + ((quad & 1) << 3) + r8;
    const int a_k = (quad >> 1) << 3;
    const uint32_t a_base0 =
        (uint32_t)__cvta_generic_to_shared(&As[a_row * ST + a_k]);
    const uint32_t a_base1 = a_base0 + 16 * ST * 2;
    // B tiles: (n+0,k+0),(n+0,k+8),(n+8,k+0),(n+8,k+8) -> b0/b1 of ni, ni+1
    const int b_row = wn * 64 + ((quad >> 1) << 3) + r8;
    const int b_k = (quad & 1) << 3;
    const uint32_t b_base =
        (uint32_t)__cvta_generic_to_shared(&Bs[b_row * ST + b_k]);

    float acc[2][8][4] = {};

    for (int kt = 0; kt < K; kt += 64) {
        // pure uint4 copy loaders: 1024 uint4 per tile, 4 per thread
        #pragma unroll
        for (int i = 0; i < 4; i++) {
            int idx = tid + (i << 8);
            int row = idx >> 3;           // 0..127
            int grp = (idx & 7) << 3;     // halves offset, 16B units
            *reinterpret_cast<uint4*>(&As[row * ST + grp]) =
                *reinterpret_cast<const uint4*>(A + (long)(m0 + row) * lda + kt + grp);
            *reinterpret_cast<uint4*>(&Bs[row * ST + grp]) =
                *reinterpret_cast<const uint4*>(B + (long)(n0 + row) * ldb + kt + grp);
        }
        __syncthreads();

        #pragma unroll
        for (int ks = 0; ks < 4; ks++) {   // 4 x k16
            const uint32_t koff = (uint32_t)ks * 32;  // 16 halves = 32 bytes

            uint32_t af[2][4];
            ldsm_x4(af[0][0], af[0][1], af[0][2], af[0][3], a_base0 + koff);
            ldsm_x4(af[1][0], af[1][1], af[1][2], af[1][3], a_base1 + koff);

            uint32_t bf[8][2];
            #pragma unroll
            for (int nip = 0; nip < 4; nip++) {
                ldsm_x4(bf[2 * nip][0], bf[2 * nip][1],
                        bf[2 * nip + 1][0], bf[2 * nip + 1][1],
                        b_base + nip * (16 * ST * 2) + koff);
            }

            #pragma unroll
            for (int mi = 0; mi < 2; mi++)
                #pragma unroll
                for (int ni = 0; ni < 8; ni++) {
                    float* c = acc[mi][ni];
                    asm volatile(
                        "mma.sync.aligned.m16n8k16.row.col.f32.f16.f16.f32 "
                        "{%0,%1,%2,%3}, {%4,%5,%6,%7}, {%8,%9}, {%0,%1,%2,%3};"
                        : "+f"(c[0]), "+f"(c[1]), "+f"(c[2]), "+f"(c[3])
                        : "r"(af[mi][0]), "r"(af[mi][1]), "r"(af[mi][2]),
                          "r"(af[mi][3]), "r"(bf[ni][0]), "r"(bf[ni][1]));
                }
        }
        __syncthreads();
    }

    #pragma unroll
    for (int mi = 0; mi < 2; mi++) {
        int r0 = m0 + wm * 32 + mi * 16 + g;
        #pragma unroll
        for (int ni = 0; ni < 8; ni++) {
            int col = n0 + wn * 64 + ni * 8 + tg * 2;
            float2 v0 = {alpha * acc[mi][ni][0], alpha * acc[mi][ni][1]};
            float2 v1 = {alpha * acc[mi][ni][2], alpha * acc[mi][ni][3]};
            *reinterpret_cast<float2*>(C + (long)r0 * ldc + col) = v0;
            *reinterpret_cast<float2*>(C + (long)(r0 + 8) * ldc + col) = v1;
        }
    }
}

// ======================= prep: img -> fp16 + fp16 transpose ================
__global__ __launch_bounds__(256)
void prep_kernel(const float* __restrict__ img, __half* __restrict__ imgh,
                 __half* __restrict__ imght) {
    __shared__ __half tile[32][33];
    const int b = blockIdx.z;
    const int n0 = blockIdx.x * 32;
    const int c0 = blockIdx.y * 32;
    const int tx = threadIdx.x & 31;
    const int ty = threadIdx.x >> 5;
    #pragma unroll
    for (int j = 0; j < 4; j++) {
        int r = ty + j * 8;
        float v = img[((long)b * 4096 + n0 + r) * 1024 + c0 + tx];
        __half h = __float2half_rn(v);
        imgh[((long)b * 4096 + n0 + r) * 1024 + c0 + tx] = h;
        tile[r][tx] = h;
    }
    __syncthreads();
    #pragma unroll
    for (int j = 0; j < 4; j++) {
        int r = ty + j * 8;
        imght[((long)b * 1024 + c0 + r) * 4096 + n0 + tx] = tile[tx][r];
    }
}

// ======================= TF32 GEMM (step 1, NT) ============================
__global__ __launch_bounds__(256)
void tf32_gemm_nt_kernel(const float* __restrict__ A, const float* __restrict__ B,
                         float* __restrict__ C, int K, int lda, int ldb, int ldc) {
    constexpr int ST = 36;
    __shared__ uint32_t As[128 * ST];
    __shared__ uint32_t Bs[128 * ST];

    const int tid = threadIdx.x;
    const int lane = tid & 31;
    const int warp = tid >> 5;
    const int g = lane >> 2;
    const int tg = lane & 3;
    const int wm = warp >> 1;
    const int wn = warp & 1;
    const int m0 = blockIdx.y * 128;
    const int n0 = blockIdx.x * 128;

    const int r8 = lane & 7;
    const int quad = lane >> 3;
    const int a_row = wm * 32 + ((quad & 1) << 3) + r8;
    const int a_cadd = (quad >> 1) << 2;
    const uint32_t a_base0 =
        (uint32_t)__cvta_generic_to_shared(&As[a_row * ST + a_cadd]);
    const uint32_t a_base1 = a_base0 + 16 * ST * 4;
    const int b_row = wn * 64 + ((quad >> 1) << 3) + r8;
    const int b_cadd = (quad & 1) << 2;
    const uint32_t b_base =
        (uint32_t)__cvta_generic_to_shared(&Bs[b_row * ST + b_cadd]);

    float acc[2][8][4] = {};

    for (int kt = 0; kt < K; kt += 32) {
        #pragma unroll
        for (int i = 0; i < 4; i++) {
            int idx = tid + i * 256;
            int row = idx >> 3;
            int cv = (idx & 7) * 4;
            float4 va = *reinterpret_cast<const float4*>(
                A + (long)(m0 + row) * lda + kt + cv);
            uint32_t* da = &As[row * ST + cv];
            da[0] = f2tf32(va.x); da[1] = f2tf32(va.y);
            da[2] = f2tf32(va.z); da[3] = f2tf32(va.w);
            float4 vb = *reinterpret_cast<const float4*>(
                B + (long)(n0 + row) * ldb + kt + cv);
            uint32_t* db = &Bs[row * ST + cv];
            db[0] = f2tf32(vb.x); db[1] = f2tf32(vb.y);
            db[2] = f2tf32(vb.z); db[3] = f2tf32(vb.w);
        }
        __syncthreads();

        #pragma unroll
        for (int ks = 0; ks < 4; ks++) {
            const uint32_t koff = (uint32_t)ks * 32;
            uint32_t af[2][4];
            ldsm_x4(af[0][0], af[0][1], af[0][2], af[0][3], a_base0 + koff);
            ldsm_x4(af[1][0], af[1][1], af[1][2], af[1][3], a_base1 + koff);
            uint32_t bf[8][2];
            #pragma unroll
            for (int nip = 0; nip < 4; nip++) {
                ldsm_x4(bf[2 * nip][0], bf[2 * nip][1],
                        bf[2 * nip + 1][0], bf[2 * nip + 1][1],
                        b_base + nip * (16 * ST * 4) + koff);
            }
            #pragma unroll
            for (int mi = 0; mi < 2; mi++)
                #pragma unroll
                for (int ni = 0; ni < 8; ni++) {
                    float* c = acc[mi][ni];
                    asm volatile(
                        "mma.sync.aligned.m16n8k8.row.col.f32.tf32.tf32.f32 "
                        "{%0,%1,%2,%3}, {%4,%5,%6,%7}, {%8,%9}, {%0,%1,%2,%3};"
                        : "+f"(c[0]), "+f"(c[1]), "+f"(c[2]), "+f"(c[3])
                        : "r"(af[mi][0]), "r"(af[mi][1]), "r"(af[mi][2]),
                          "r"(af[mi][3]), "r"(bf[ni][0]), "r"(bf[ni][1]));
                }
        }
        __syncthreads();
    }

    #pragma unroll
    for (int mi = 0; mi < 2; mi++) {
        int r0 = m0 + wm * 32 + mi * 16 + g;
        #pragma unroll
        for (int ni = 0; ni < 8; ni++) {
            int col = n0 + wn * 64 + ni * 8 + tg * 2;
            float2 v0 = {acc[mi][ni][0], acc[mi][ni][1]};
            float2 v1 = {acc[mi][ni][2], acc[mi][ni][3]};
            *reinterpret_cast<float2*>(C + (long)r0 * ldc + col) = v0;
            *reinterpret_cast<float2*>(C + (long)(r0 + 8) * ldc + col) = v1;
        }
    }
}

// ======================= fp32 SGEMM (steps 2, 6) ===========================
template <int BM, int BN, int BK, int TM, int TN, bool TRANSB, bool OUT_HALF>
__global__ __launch_bounds__((BM / TM) * (BN / TN))
void sgemm_kernel(const float* __restrict__ Ag, const float* __restrict__ Bg,
                  void* __restrict__ Cg,
                  int M, int N, int K, int lda, int ldb, int ldc,
                  long aOff1, long aOff2, long bOff1, long bOff2,
                  long cOff1, long cOff2, int Z2, float alpha) {
    constexpr int THREADS = (BM / TM) * (BN / TN);
    const int z = blockIdx.z;
    const int z1 = z / Z2;
    const int z2 = z - z1 * Z2;
    const float* A = Ag + (long)z1 * aOff1 + (long)z2 * aOff2;
    const float* B = Bg + (long)z1 * bOff1 + (long)z2 * bOff2;

    __shared__ __align__(16) float As[BK][BM];
    __shared__ __align__(16) float Bs[BK][BN];

    const int tid = threadIdx.x;
    const int m0 = blockIdx.y * BM;
    const int n0 = blockIdx.x * BN;
    const int tm0 = (tid / (BN / TN)) * TM;
    const int tn0 = (tid % (BN / TN)) * TN;

    float acc[TM][TN] = {};

    constexpr int KV = BK / 4;
    constexpr int A_PER = (BM * KV) / THREADS;

    for (int kt = 0; kt < K; kt += BK) {
        #pragma unroll
        for (int i = 0; i < A_PER; i++) {
            int idx = tid + i * THREADS;
            int row = idx / KV;
            int cv = idx - row * KV;
            float4 v = *reinterpret_cast<const float4*>(
                A + (long)(m0 + row) * lda + kt + cv * 4);
            As[cv * 4 + 0][row] = v.x;
            As[cv * 4 + 1][row] = v.y;
            As[cv * 4 + 2][row] = v.z;
            As[cv * 4 + 3][row] = v.w;
        }
        if constexpr (TRANSB) {
            constexpr int B_PER = (BN * KV) / THREADS;
            #pragma unroll
            for (int i = 0; i < B_PER; i++) {
                int idx = tid + i * THREADS;
                int row = idx / KV;
                int cv = idx - row * KV;
                float4 v = *reinterpret_cast<const float4*>(
                    B + (long)(n0 + row) * ldb + kt + cv * 4);
                Bs[cv * 4 + 0][row] = v.x;
                Bs[cv * 4 + 1][row] = v.y;
                Bs[cv * 4 + 2][row] = v.z;
                Bs[cv * 4 + 3][row] = v.w;
            }
        } else {
            constexpr int NV = BN / 4;
            constexpr int B_PER = (BK * NV) / THREADS;
            #pragma unroll
            for (int i = 0; i < B_PER; i++) {
                int idx = tid + i * THREADS;
                int row = idx / NV;
                int cv = idx - row * NV;
                float4 v = *reinterpret_cast<const float4*>(
                    B + (long)(kt + row) * ldb + n0 + cv * 4);
                *reinterpret_cast<float4*>(&Bs[row][cv * 4]) = v;
            }
        }
        __syncthreads();

        #pragma unroll
        for (int kk = 0; kk < BK; kk++) {
            float ra[TM], rb[TN];
            #pragma unroll
            for (int i = 0; i < TM / 4; i++)
                *reinterpret_cast<float4*>(&ra[i * 4]) =
                    *reinterpret_cast<const float4*>(&As[kk][tm0 + i * 4]);
            #pragma unroll
            for (int j = 0; j < TN / 4; j++)
                *reinterpret_cast<float4*>(&rb[j * 4]) =
                    *reinterpret_cast<const float4*>(&Bs[kk][tn0 + j * 4]);
            #pragma unroll
            for (int i = 0; i < TM; i++)
                #pragma unroll
                for (int j = 0; j < TN; j++)
                    acc[i][j] = fmaf(ra[i], rb[j], acc[i][j]);
        }
        __syncthreads();
    }

    if constexpr (OUT_HALF) {
        __half* C = (__half*)Cg + (long)z1 * cOff1 + (long)z2 * cOff2;
        #pragma unroll
        for (int i = 0; i < TM; i++)
            #pragma unroll
            for (int j = 0; j < TN / 4; j++) {
                __half2 h0 = __floats2half2_rn(alpha * acc[i][j * 4 + 0],
                                               alpha * acc[i][j * 4 + 1]);
                __half2 h1 = __floats2half2_rn(alpha * acc[i][j * 4 + 2],
                                               alpha * acc[i][j * 4 + 3]);
                uint2 u = {h2bits(h0), h2bits(h1)};
                *reinterpret_cast<uint2*>(
                    C + (long)(m0 + tm0 + i) * ldc + n0 + tn0 + j * 4) = u;
            }
    } else {
        float* C = (float*)Cg + (long)z1 * cOff1 + (long)z2 * cOff2;
        #pragma unroll
        for (int i = 0; i < TM; i++)
            #pragma unroll
            for (int j = 0; j < TN / 4; j++) {
                float4 v;
                v.x = alpha * acc[i][j * 4 + 0];
                v.y = alpha * acc[i][j * 4 + 1];
                v.z = alpha * acc[i][j * 4 + 2];
                v.w = alpha * acc[i][j * 4 + 3];
                *reinterpret_cast<float4*>(
                    C + (long)(m0 + tm0 + i) * ldc + n0 + tn0 + j * 4) = v;
            }
    }
}

// ======================= softmax (fp32 in, fp16 out) =======================
__global__ __launch_bounds__(256)
void softmax4096_kernel(const float* __restrict__ S, __half* __restrict__ Sh) {
    const float* row = S + (size_t)blockIdx.x * 4096;
    __half* rowh = Sh + (size_t)blockIdx.x * 4096;
    const int tid = threadIdx.x;
    __shared__ float red[8];

    float4 v[4];
    float maxv = -3.4e38f;
    #pragma unroll
    for (int i = 0; i < 4; i++) {
        v[i] = reinterpret_cast<const float4*>(row)[tid + i * 256];
        maxv = fmaxf(maxv, fmaxf(fmaxf(v[i].x, v[i].y), fmaxf(v[i].z, v[i].w)));
    }
    #pragma unroll
    for (int o = 16; o > 0; o >>= 1)
        maxv = fmaxf(maxv, __shfl_xor_sync(0xffffffffu, maxv, o));
    if ((tid & 31) == 0) red[tid >> 5] = maxv;
    __syncthreads();
    float bm = red[0];
    #pragma unroll
    for (int i = 1; i < 8; i++) bm = fmaxf(bm, red[i]);

    float sum = 0.f;
    #pragma unroll
    for (int i = 0; i < 4; i++) {
        v[i].x = __expf(v[i].x - bm);
        v[i].y = __expf(v[i].y - bm);
        v[i].z = __expf(v[i].z - bm);
        v[i].w = __expf(v[i].w - bm);
        sum += (v[i].x + v[i].y) + (v[i].z + v[i].w);
    }
    __syncthreads();
    #pragma unroll
    for (int o = 16; o > 0; o >>= 1) sum += __shfl_xor_sync(0xffffffffu, sum, o);
    if ((tid & 31) == 0) red[tid >> 5] = sum;
    __syncthreads();
    float tot = 0.f;
    #pragma unroll
    for (int i = 0; i < 8; i++) tot += red[i];
    const float inv = 1.0f / tot;
    #pragma unroll
    for (int i = 0; i < 4; i++) {
        __half2 h0 = __floats2half2_rn(v[i].x * inv, v[i].y * inv);
        __half2 h1 = __floats2half2_rn(v[i].z * inv, v[i].w * inv);
        uint2 u = {h2bits(h0), h2bits(h1)};
        reinterpret_cast<uint2*>(rowh)[tid + i * 256] = u;
    }
}

extern "C" void kernel_launch(void* const* d_in, const int* in_sizes, int n_in,
                              void* d_out, int out_size) {
    const float* img = (const float*)d_in[0];  // (16,4096,1024)
    const float* aud = (const float*)d_in[1];  // (16,64,1024)
    const float* Wq = (const float*)d_in[2];   // (1024,1024)
    const float* Wk = (const float*)d_in[3];
    const float* Wv = (const float*)d_in[4];
    float* out = (float*)d_out;                // (16,64,1024)

    float *q, *sc, *t;
    __half *qth, *sch, *imgh, *imght;
    cudaGetSymbolAddress((void**)&q, g_q);
    cudaGetSymbolAddress((void**)&qth, g_qth);
    cudaGetSymbolAddress((void**)&sc, g_sc);
    cudaGetSymbolAddress((void**)&sch, g_sch);
    cudaGetSymbolAddress((void**)&imgh, g_imgh);
    cudaGetSymbolAddress((void**)&imght, g_imght);
    cudaGetSymbolAddress((void**)&t, g_t);

    const float scale = 0.08838834764831845f;  // (1024/8)^-0.5

    // 0) img -> fp16 (row-major) + fp16 transpose per batch
    prep_kernel<<<dim3(128, 32, 16), 256>>>(img, imgh, imght);

    // 1) q = aud @ Wq^T : M=1024, N=1024, K=1024 (tf32 NT) -> fp32
    tf32_gemm_nt_kernel<<<dim3(8, 8, 1), 256>>>(aud, Wq, q, 1024, 1024, 1024, 1024);

    // 2) qt_h[b,h] = Q_bh @ Wk_h : M=64, N=1024, K=128 (fp32 NN -> fp16 out)
    sgemm_kernel<64, 64, 16, 4, 4, false, true><<<dim3(16, 1, 128), 256>>>(
        q, Wk, qth, 64, 1024, 128, 1024, 1024, 1024,
        65536, 128, 0, 131072, 524288, 65536, 8, 1.0f);

    // 3) sc_b = qt_b @ img_b^T * scale : M=512, N=4096, K=1024 (fp16 NT)
    h16_gemm_nt_kernel<<<dim3(32, 4, 16), 256>>>(
        qth, imgh, sc, 1024, 1024, 1024, 4096,
        524288, 4194304, 2097152, scale);

    // 4) softmax rows (fp32 -> fp16)
    softmax4096_kernel<<<16 * 512, 256>>>(sc, sch);

    // 5) t_b = P_b @ img_b : M=512, N=1024, K=4096 (fp16 NT via img^T)
    h16_gemm_nt_kernel<<<dim3(8, 4, 16), 256>>>(
        sch, imght, t, 4096, 4096, 4096, 1024,
        2097152, 4194304, 524288, 1.0f);

    // 6) out[b,:,h*128:(h+1)*128] = t_bh @ Wv_h^T (fp32 NT)
    sgemm_kernel<64, 64, 16, 4, 4, true, false><<<dim3(2, 1, 128), 256>>>(
        t, Wv, out, 64, 128, 1024, 1024, 1024, 1024,
        524288, 65536, 0, 131072, 65536, 128, 8, 1.0f);
}

// round 14
// speedup vs baseline: 1.8035x; 1.1429x over previous
#include <cuda_runtime.h>
#include <cuda_fp16.h>
#include <cstdint>

// ---------------------------------------------------------------------------
// Cross-modal attention, aq=1, softmax=1, sigmoid=0.
// B=16, N=4096, Kq=64, C=1024, H=8, d=128. Output (16,64,1024) fp32.
//
//   0) prep: img_h = fp16(img); img_ht = fp16(img^T per batch)
//   1) q    = aud @ Wq^T          (1024x1024x1024) NT  [tf32 mma] -> fp32
//   2) qt_h = Q_bh @ Wk_h         (64x1024x128)x128 NN [fp32]     -> fp16
//   3) sc_b = qt_b @ img_b^T * s  (512x4096x1024)x16  [fp16 mma NT]
//   4) softmax rows (fp32 -> fp16)
//   5) t_b  = sc_b @ img_b        (512x1024x4096)x16  [fp16 mma NT via img^T]
//   6) out  = t_bh @ Wv_h^T       (64x128x1024)x128 NT [fp32]
//
// R13: fix R12's stage-size constant (halves vs bytes smem OOB).
//      2-stage cp.async.cg pipeline, 73728B dynamic smem, launch_bounds(256,2).
// ---------------------------------------------------------------------------

__device__ __align__(16) float  g_q[16 * 64 * 1024];          //   4 MB
__device__ __align__(16) __half g_qth[16 * 8 * 64 * 1024];    //  16 MB
__device__ __align__(16) float  g_sc[16 * 512 * 4096];        // 128 MB
__device__ __align__(16) __half g_sch[16 * 512 * 4096];       //  64 MB
__device__ __align__(16) __half g_imgh[16 * 4096 * 1024];     // 128 MB
__device__ __align__(16) __half g_imght[16 * 1024 * 4096];    // 128 MB
__device__ __align__(16) float  g_t[16 * 8 * 64 * 1024];      //  32 MB

__device__ __forceinline__ uint32_t f2tf32(float x) {
    uint32_t r;
    asm("cvt.rna.tf32.f32 %0, %1;" : "=r"(r) : "f"(x));
    return r;
}
__device__ __forceinline__ void ldsm_x4(uint32_t& r0, uint32_t& r1,
                                        uint32_t& r2, uint32_t& r3,
                                        uint32_t addr) {
    asm volatile(
        "ldmatrix.sync.aligned.m8n8.x4.shared.b16 {%0,%1,%2,%3}, [%4];"
        : "=r"(r0), "=r"(r1), "=r"(r2), "=r"(r3) : "r"(addr));
}
__device__ __forceinline__ uint32_t h2bits(__half2 h) {
    return *reinterpret_cast<uint32_t*>(&h);
}
__device__ __forceinline__ void cp16(uint32_t dst, const void* src) {
    asm volatile("cp.async.cg.shared.global [%0], [%1], 16;"
                 :: "r"(dst), "l"(src));
}

// ======================= FP16-input NT tensor GEMM =========================
// C[M,N] = alpha * A[M,K] * B[N,K]^T, A/B fp16 row-major (K contiguous),
// fp32 accumulate. Block tile 128x128x64, 8 warps (4x2), warp 32x64, k16 mma.
// 2-stage cp.async pipeline.
// Per-stage BYTES: A tile 128*72*2 = 18432, B tile 18432 -> stage = 36864.
static const int H16_TILE_B = 128 * 72 * 2;       // 18432 bytes per operand tile
static const int H16_STAGE = 2 * H16_TILE_B;      // 36864 bytes per stage
static const int H16_SMEM = 2 * H16_STAGE;        // 73728 bytes total

__global__ __launch_bounds__(256, 2)
void h16_gemm_nt_kernel(const __half* __restrict__ Ag,
                        const __half* __restrict__ Bg,
                        float* __restrict__ Cg,
                        int K, int lda, int ldb, int ldc,
                        long aOff, long bOff, long cOff, float alpha) {
    constexpr int ST = 72;
    extern __shared__ __align__(16) __half smh[];
    const __half* A = Ag + (long)blockIdx.z * aOff;
    const __half* B = Bg + (long)blockIdx.z * bOff;
    float* C = Cg + (long)blockIdx.z * cOff;

    const int tid = threadIdx.x;
    const int lane = tid & 31;
    const int warp = tid >> 5;
    const int g = lane >> 2;
    const int tg = lane & 3;
    const int wm = warp >> 1;     // 0..3 -> warp row * 32
    const int wn = warp & 1;      // 0..1 -> warp col * 64
    const int m0 = blockIdx.y * 128;
    const int n0 = blockIdx.x * 128;

    const uint32_t sbase = (uint32_t)__cvta_generic_to_shared(smh);

    // ldmatrix per-lane fragment offsets (within a stage)
    const int r8 = lane & 7;
    const int quad = lane >> 3;
    const int a_row = wm * 32 + ((quad & 1) << 3) + r8;
    const int a_k = (quad >> 1) << 3;
    const uint32_t a_foff = (uint32_t)(a_row * ST + a_k) * 2;
    const int b_row = wn * 64 + ((quad >> 1) << 3) + r8;
    const int b_k = (quad & 1) << 3;
    const uint32_t b_foff = (uint32_t)H16_TILE_B + (uint32_t)(b_row * ST + b_k) * 2;

    float acc[2][8][4] = {};

    const int niter = K >> 6;

    // ---- prologue: stage 0 loads ----
    {
        const uint32_t aoff = sbase;
        const uint32_t boff = sbase + (uint32_t)H16_TILE_B;
        #pragma unroll
        for (int i = 0; i < 4; i++) {
            int idx = tid + (i << 8);
            int row = idx >> 3;
            int grp = (idx & 7) << 3;
            cp16(aoff + (uint32_t)(row * ST + grp) * 2,
                 A + (long)(m0 + row) * lda + grp);
            cp16(boff + (uint32_t)(row * ST + grp) * 2,
                 B + (long)(n0 + row) * ldb + grp);
        }
        asm volatile("cp.async.commit_group;");
    }

    for (int it = 0; it < niter; ++it) {
        const int s = it & 1;

        // issue next stage loads, then drain current stage
        if (it + 1 < niter) {
            const int kt = (it + 1) << 6;
            const uint32_t aoff = sbase + (uint32_t)(s ^ 1) * (uint32_t)H16_STAGE;
            const uint32_t boff = aoff + (uint32_t)H16_TILE_B;
            #pragma unroll
            for (int i = 0; i < 4; i++) {
                int idx = tid + (i << 8);
                int row = idx >> 3;
                int grp = (idx & 7) << 3;
                cp16(aoff + (uint32_t)(row * ST + grp) * 2,
                     A + (long)(m0 + row) * lda + kt + grp);
                cp16(boff + (uint32_t)(row * ST + grp) * 2,
                     B + (long)(n0 + row) * ldb + kt + grp);
            }
            asm volatile("cp.async.commit_group;");
            asm volatile("cp.async.wait_group 1;");
        } else {
            asm volatile("cp.async.wait_group 0;");
        }
        __syncthreads();

        const uint32_t stg = sbase + (uint32_t)s * (uint32_t)H16_STAGE;
        const uint32_t a_base0 = stg + a_foff;
        const uint32_t a_base1 = a_base0 + 16 * ST * 2;
        const uint32_t b_base = stg + b_foff;

        #pragma unroll
        for (int ks = 0; ks < 4; ks++) {   // 4 x k16
            const uint32_t koff = (uint32_t)ks * 32;  // 16 halves = 32 bytes

            uint32_t af[2][4];
            ldsm_x4(af[0][0], af[0][1], af[0][2], af[0][3], a_base0 + koff);
            ldsm_x4(af[1][0], af[1][1], af[1][2], af[1][3], a_base1 + koff);

            uint32_t bf[8][2];
            #pragma unroll
            for (int nip = 0; nip < 4; nip++) {
                ldsm_x4(bf[2 * nip][0], bf[2 * nip][1],
                        bf[2 * nip + 1][0], bf[2 * nip + 1][1],
                        b_base + nip * (16 * ST * 2) + koff);
            }

            #pragma unroll
            for (int mi = 0; mi < 2; mi++)
                #pragma unroll
                for (int ni = 0; ni < 8; ni++) {
                    float* c = acc[mi][ni];
                    asm volatile(
                        "mma.sync.aligned.m16n8k16.row.col.f32.f16.f16.f32 "
                        "{%0,%1,%2,%3}, {%4,%5,%6,%7}, {%8,%9}, {%0,%1,%2,%3};"
                        : "+f"(c[0]), "+f"(c[1]), "+f"(c[2]), "+f"(c[3])
                        : "r"(af[mi][0]), "r"(af[mi][1]), "r"(af[mi][2]),
                          "r"(af[mi][3]), "r"(bf[ni][0]), "r"(bf[ni][1]));
                }
        }
        __syncthreads();
    }

    #pragma unroll
    for (int mi = 0; mi < 2; mi++) {
        int r0 = m0 + wm * 32 + mi * 16 + g;
        #pragma unroll
        for (int ni = 0; ni < 8; ni++) {
            int col = n0 + wn * 64 + ni * 8 + tg * 2;
            float2 v0 = {alpha * acc[mi][ni][0], alpha * acc[mi][ni][1]};
            float2 v1 = {alpha * acc[mi][ni][2], alpha * acc[mi][ni][3]};
            *reinterpret_cast<float2*>(C + (long)r0 * ldc + col) = v0;
            *reinterpret_cast<float2*>(C + (long)(r0 + 8) * ldc + col) = v1;
        }
    }
}

// ======================= prep: img -> fp16 + fp16 transpose ================
__global__ __launch_bounds__(256)
void prep_kernel(const float* __restrict__ img, __half* __restrict__ imgh,
                 __half* __restrict__ imght) {
    __shared__ __half tile[32][33];
    const int b = blockIdx.z;
    const int n0 = blockIdx.x * 32;
    const int c0 = blockIdx.y * 32;
    const int tx = threadIdx.x & 31;
    const int ty = threadIdx.x >> 5;
    #pragma unroll
    for (int j = 0; j < 4; j++) {
        int r = ty + j * 8;
        float v = img[((long)b * 4096 + n0 + r) * 1024 + c0 + tx];
        __half h = __float2half_rn(v);
        imgh[((long)b * 4096 + n0 + r) * 1024 + c0 + tx] = h;
        tile[r][tx] = h;
    }
    __syncthreads();
    #pragma unroll
    for (int j = 0; j < 4; j++) {
        int r = ty + j * 8;
        imght[((long)b * 1024 + c0 + r) * 4096 + n0 + tx] = tile[tx][r];
    }
}

// ======================= TF32 GEMM (step 1, NT) ============================
__global__ __launch_bounds__(256)
void tf32_gemm_nt_kernel(const float* __restrict__ A, const float* __restrict__ B,
                         float* __restrict__ C, int K, int lda, int ldb, int ldc) {
    constexpr int ST = 36;
    __shared__ uint32_t As[128 * ST];
    __shared__ uint32_t Bs[128 * ST];

    const int tid = threadIdx.x;
    const int lane = tid & 31;
    const int warp = tid >> 5;
    const int g = lane >> 2;
    const int tg = lane & 3;
    const int wm = warp >> 1;
    const int wn = warp & 1;
    const int m0 = blockIdx.y * 128;
    const int n0 = blockIdx.x * 128;

    const int r8 = lane & 7;
    const int quad = lane >> 3;
    const int a_row = wm * 32 + ((quad & 1) << 3) + r8;
    const int a_cadd = (quad >> 1) << 2;
    const uint32_t a_base0 =
        (uint32_t)__cvta_generic_to_shared(&As[a_row * ST + a_cadd]);
    const uint32_t a_base1 = a_base0 + 16 * ST * 4;
    const int b_row = wn * 64 + ((quad >> 1) << 3) + r8;
    const int b_cadd = (quad & 1) << 2;
    const uint32_t b_base =
        (uint32_t)__cvta_generic_to_shared(&Bs[b_row * ST + b_cadd]);

    float acc[2][8][4] = {};

    for (int kt = 0; kt < K; kt += 32) {
        #pragma unroll
        for (int i = 0; i < 4; i++) {
            int idx = tid + i * 256;
            int row = idx >> 3;
            int cv = (idx & 7) * 4;
            float4 va = *reinterpret_cast<const float4*>(
                A + (long)(m0 + row) * lda + kt + cv);
            uint32_t* da = &As[row * ST + cv];
            da[0] = f2tf32(va.x); da[1] = f2tf32(va.y);
            da[2] = f2tf32(va.z); da[3] = f2tf32(va.w);
            float4 vb = *reinterpret_cast<const float4*>(
                B + (long)(n0 + row) * ldb + kt + cv);
            uint32_t* db = &Bs[row * ST + cv];
            db[0] = f2tf32(vb.x); db[1] = f2tf32(vb.y);
            db[2] = f2tf32(vb.z); db[3] = f2tf32(vb.w);
        }
        __syncthreads();

        #pragma unroll
        for (int ks = 0; ks < 4; ks++) {
            const uint32_t koff = (uint32_t)ks * 32;
            uint32_t af[2][4];
            ldsm_x4(af[0][0], af[0][1], af[0][2], af[0][3], a_base0 + koff);
            ldsm_x4(af[1][0], af[1][1], af[1][2], af[1][3], a_base1 + koff);
            uint32_t bf[8][2];
            #pragma unroll
            for (int nip = 0; nip < 4; nip++) {
                ldsm_x4(bf[2 * nip][0], bf[2 * nip][1],
                        bf[2 * nip + 1][0], bf[2 * nip + 1][1],
                        b_base + nip * (16 * ST * 4) + koff);
            }
            #pragma unroll
            for (int mi = 0; mi < 2; mi++)
                #pragma unroll
                for (int ni = 0; ni < 8; ni++) {
                    float* c = acc[mi][ni];
                    asm volatile(
                        "mma.sync.aligned.m16n8k8.row.col.f32.tf32.tf32.f32 "
                        "{%0,%1,%2,%3}, {%4,%5,%6,%7}, {%8,%9}, {%0,%1,%2,%3};"
                        : "+f"(c[0]), "+f"(c[1]), "+f"(c[2]), "+f"(c[3])
                        : "r"(af[mi][0]), "r"(af[mi][1]), "r"(af[mi][2]),
                          "r"(af[mi][3]), "r"(bf[ni][0]), "r"(bf[ni][1]));
                }
        }
        __syncthreads();
    }

    #pragma unroll
    for (int mi = 0; mi < 2; mi++) {
        int r0 = m0 + wm * 32 + mi * 16 + g;
        #pragma unroll
        for (int ni = 0; ni < 8; ni++) {
            int col = n0 + wn * 64 + ni * 8 + tg * 2;
            float2 v0 = {acc[mi][ni][0], acc[mi][ni][1]};
            float2 v1 = {acc[mi][ni][2], acc[mi][ni][3]};
            *reinterpret_cast<float2*>(C + (long)r0 * ldc + col) = v0;
            *reinterpret_cast<float2*>(C + (long)(r0 + 8) * ldc + col) = v1;
        }
    }
}

// ======================= fp32 SGEMM (steps 2, 6) ===========================
template <int BM, int BN, int BK, int TM, int TN, bool TRANSB, bool OUT_HALF>
__global__ __launch_bounds__((BM / TM) * (BN / TN))
void sgemm_kernel(const float* __restrict__ Ag, const float* __restrict__ Bg,
                  void* __restrict__ Cg,
                  int M, int N, int K, int lda, int ldb, int ldc,
                  long aOff1, long aOff2, long bOff1, long bOff2,
                  long cOff1, long cOff2, int Z2, float alpha) {
    constexpr int THREADS = (BM / TM) * (BN / TN);
    const int z = blockIdx.z;
    const int z1 = z / Z2;
    const int z2 = z - z1 * Z2;
    const float* A = Ag + (long)z1 * aOff1 + (long)z2 * aOff2;
    const float* B = Bg + (long)z1 * bOff1 + (long)z2 * bOff2;

    __shared__ __align__(16) float As[BK][BM];
    __shared__ __align__(16) float Bs[BK][BN];

    const int tid = threadIdx.x;
    const int m0 = blockIdx.y * BM;
    const int n0 = blockIdx.x * BN;
    const int tm0 = (tid / (BN / TN)) * TM;
    const int tn0 = (tid % (BN / TN)) * TN;

    float acc[TM][TN] = {};

    constexpr int KV = BK / 4;
    constexpr int A_PER = (BM * KV) / THREADS;

    for (int kt = 0; kt < K; kt += BK) {
        #pragma unroll
        for (int i = 0; i < A_PER; i++) {
            int idx = tid + i * THREADS;
            int row = idx / KV;
            int cv = idx - row * KV;
            float4 v = *reinterpret_cast<const float4*>(
                A + (long)(m0 + row) * lda + kt + cv * 4);
            As[cv * 4 + 0][row] = v.x;
            As[cv * 4 + 1][row] = v.y;
            As[cv * 4 + 2][row] = v.z;
            As[cv * 4 + 3][row] = v.w;
        }
        if constexpr (TRANSB) {
            constexpr int B_PER = (BN * KV) / THREADS;
            #pragma unroll
            for (int i = 0; i < B_PER; i++) {
                int idx = tid + i * THREADS;
                int row = idx / KV;
                int cv = idx - row * KV;
                float4 v = *reinterpret_cast<const float4*>(
                    B + (long)(n0 + row) * ldb + kt + cv * 4);
                Bs[cv * 4 + 0][row] = v.x;
                Bs[cv * 4 + 1][row] = v.y;
                Bs[cv * 4 + 2][row] = v.z;
                Bs[cv * 4 + 3][row] = v.w;
            }
        } else {
            constexpr int NV = BN / 4;
            constexpr int B_PER = (BK * NV) / THREADS;
            #pragma unroll
            for (int i = 0; i < B_PER; i++) {
                int idx = tid + i * THREADS;
                int row = idx / NV;
                int cv = idx - row * NV;
                float4 v = *reinterpret_cast<const float4*>(
                    B + (long)(kt + row) * ldb + n0 + cv * 4);
                *reinterpret_cast<float4*>(&Bs[row][cv * 4]) = v;
            }
        }
        __syncthreads();

        #pragma unroll
        for (int kk = 0; kk < BK; kk++) {
            float ra[TM], rb[TN];
            #pragma unroll
            for (int i = 0; i < TM / 4; i++)
                *reinterpret_cast<float4*>(&ra[i * 4]) =
                    *reinterpret_cast<const float4*>(&As[kk][tm0 + i * 4]);
            #pragma unroll
            for (int j = 0; j < TN / 4; j++)
                *reinterpret_cast<float4*>(&rb[j * 4]) =
                    *reinterpret_cast<const float4*>(&Bs[kk][tn0 + j * 4]);
            #pragma unroll
            for (int i = 0; i < TM; i++)
                #pragma unroll
                for (int j = 0; j < TN; j++)
                    acc[i][j] = fmaf(ra[i], rb[j], acc[i][j]);
        }
        __syncthreads();
    }

    if constexpr (OUT_HALF) {
        __half* C = (__half*)Cg + (long)z1 * cOff1 + (long)z2 * cOff2;
        #pragma unroll
        for (int i = 0; i < TM; i++)
            #pragma unroll
            for (int j = 0; j < TN / 4; j++) {
                __half2 h0 = __floats2half2_rn(alpha * acc[i][j * 4 + 0],
                                               alpha * acc[i][j * 4 + 1]);
                __half2 h1 = __floats2half2_rn(alpha * acc[i][j * 4 + 2],
                                               alpha * acc[i][j * 4 + 3]);
                uint2 u = {h2bits(h0), h2bits(h1)};
                *reinterpret_cast<uint2*>(
                    C + (long)(m0 + tm0 + i) * ldc + n0 + tn0 + j * 4) = u;
            }
    } else {
        float* C = (float*)Cg + (long)z1 * cOff1 + (long)z2 * cOff2;
        #pragma unroll
        for (int i = 0; i < TM; i++)
            #pragma unroll
            for (int j = 0; j < TN / 4; j++) {
                float4 v;
                v.x = alpha * acc[i][j * 4 + 0];
                v.y = alpha * acc[i][j * 4 + 1];
                v.z = alpha * acc[i][j * 4 + 2];
                v.w = alpha * acc[i][j * 4 + 3];
                *reinterpret_cast<float4*>(
                    C + (long)(m0 + tm0 + i) * ldc + n0 + tn0 + j * 4) = v;
            }
    }
}

// ======================= softmax (fp32 in, fp16 out) =======================
__global__ __launch_bounds__(256)
void softmax4096_kernel(const float* __restrict__ S, __half* __restrict__ Sh) {
    const float* row = S + (size_t)blockIdx.x * 4096;
    __half* rowh = Sh + (size_t)blockIdx.x * 4096;
    const int tid = threadIdx.x;
    __shared__ float red[8];

    float4 v[4];
    float maxv = -3.4e38f;
    #pragma unroll
    for (int i = 0; i < 4; i++) {
        v[i] = reinterpret_cast<const float4*>(row)[tid + i * 256];
        maxv = fmaxf(maxv, fmaxf(fmaxf(v[i].x, v[i].y), fmaxf(v[i].z, v[i].w)));
    }
    #pragma unroll
    for (int o = 16; o > 0; o >>= 1)
        maxv = fmaxf(maxv, __shfl_xor_sync(0xffffffffu, maxv, o));
    if ((tid & 31) == 0) red[tid >> 5] = maxv;
    __syncthreads();
    float bm = red[0];
    #pragma unroll
    for (int i = 1; i < 8; i++) bm = fmaxf(bm, red[i]);

    float sum = 0.f;
    #pragma unroll
    for (int i = 0; i < 4; i++) {
        v[i].x = __expf(v[i].x - bm);
        v[i].y = __expf(v[i].y - bm);
        v[i].z = __expf(v[i].z - bm);
        v[i].w = __expf(v[i].w - bm);
        sum += (v[i].x + v[i].y) + (v[i].z + v[i].w);
    }
    __syncthreads();
    #pragma unroll
    for (int o = 16; o > 0; o >>= 1) sum += __shfl_xor_sync(0xffffffffu, sum, o);
    if ((tid & 31) == 0) red[tid >> 5] = sum;
    __syncthreads();
    float tot = 0.f;
    #pragma unroll
    for (int i = 0; i < 8; i++) tot += red[i];
    const float inv = 1.0f / tot;
    #pragma unroll
    for (int i = 0; i < 4; i++) {
        __half2 h0 = __floats2half2_rn(v[i].x * inv, v[i].y * inv);
        __half2 h1 = __floats2half2_rn(v[i].z * inv, v[i].w * inv);
        uint2 u = {h2bits(h0), h2bits(h1)};
        reinterpret_cast<uint2*>(rowh)[tid + i * 256] = u;
    }
}

extern "C" void kernel_launch(void* const* d_in, const int* in_sizes, int n_in,
                              void* d_out, int out_size) {
    const float* img = (const float*)d_in[0];  // (16,4096,1024)
    const float* aud = (const float*)d_in[1];  // (16,64,1024)
    const float* Wq = (const float*)d_in[2];   // (1024,1024)
    const float* Wk = (const float*)d_in[3];
    const float* Wv = (const float*)d_in[4];
    float* out = (float*)d_out;                // (16,64,1024)

    float *q, *sc, *t;
    __half *qth, *sch, *imgh, *imght;
    cudaGetSymbolAddress((void**)&q, g_q);
    cudaGetSymbolAddress((void**)&qth, g_qth);
    cudaGetSymbolAddress((void**)&sc, g_sc);
    cudaGetSymbolAddress((void**)&sch, g_sch);
    cudaGetSymbolAddress((void**)&imgh, g_imgh);
    cudaGetSymbolAddress((void**)&imght, g_imght);
    cudaGetSymbolAddress((void**)&t, g_t);

    cudaFuncSetAttribute(h16_gemm_nt_kernel,
                         cudaFuncAttributeMaxDynamicSharedMemorySize, H16_SMEM);

    const float scale = 0.08838834764831845f;  // (1024/8)^-0.5

    // 0) img -> fp16 (row-major) + fp16 transpose per batch
    prep_kernel<<<dim3(128, 32, 16), 256>>>(img, imgh, imght);

    // 1) q = aud @ Wq^T : M=1024, N=1024, K=1024 (tf32 NT) -> fp32
    tf32_gemm_nt_kernel<<<dim3(8, 8, 1), 256>>>(aud, Wq, q, 1024, 1024, 1024, 1024);

    // 2) qt_h[b,h] = Q_bh @ Wk_h : M=64, N=1024, K=128 (fp32 NN -> fp16 out)
    sgemm_kernel<64, 64, 16, 4, 4, false, true><<<dim3(16, 1, 128), 256>>>(
        q, Wk, qth, 64, 1024, 128, 1024, 1024, 1024,
        65536, 128, 0, 131072, 524288, 65536, 8, 1.0f);

    // 3) sc_b = qt_b @ img_b^T * scale : M=512, N=4096, K=1024 (fp16 NT)
    h16_gemm_nt_kernel<<<dim3(32, 4, 16), 256, H16_SMEM>>>(
        qth, imgh, sc, 1024, 1024, 1024, 4096,
        524288, 4194304, 2097152, scale);

    // 4) softmax rows (fp32 -> fp16)
    softmax4096_kernel<<<16 * 512, 256>>>(sc, sch);

    // 5) t_b = P_b @ img_b : M=512, N=1024, K=4096 (fp16 NT via img^T)
    h16_gemm_nt_kernel<<<dim3(8, 4, 16), 256, H16_SMEM>>>(
        sch, imght, t, 4096, 4096, 4096, 1024,
        2097152, 4194304, 524288, 1.0f);

    // 6) out[b,:,h*128:(h+1)*128] = t_bh @ Wv_h^T (fp32 NT)
    sgemm_kernel<64, 64, 16, 4, 4, true, false><<<dim3(2, 1, 128), 256>>>(
        t, Wv, out, 64, 128, 1024, 1024, 1024, 1024,
        524288, 65536, 0, 131072, 65536, 128, 8, 1.0f);
}

// round 15
// speedup vs baseline: 1.8193x; 1.0088x over previous
#include <cuda_runtime.h>
#include <cuda_fp16.h>
#include <cstdint>

// ---------------------------------------------------------------------------
// Cross-modal attention, aq=1, softmax=1, sigmoid=0.
// B=16, N=4096, Kq=64, C=1024, H=8, d=128. Output (16,64,1024) fp32.
//
//   0) prep: img_h = fp16(img); img_ht = fp16(img^T per batch)
//   1) q    = aud @ Wq^T          (1024x1024x1024) NT  [tf32 mma] -> fp32
//   2) qt_h = Q_bh @ Wk_h         (64x1024x128)x128 NN [fp32]     -> fp16
//   3) sc_b = qt_b @ img_b^T * s  (512x4096x1024)x16  [fp16 mma NT]
//   4) softmax rows (fp32 -> fp16)
//   5) t_b  = sc_b @ img_b        (512x1024x4096)x16  [fp16 mma NT via img^T]
//   6) out  = t_bh @ Wv_h^T       (64x128x1024)x128 NT [fp32]
//
// R15: 3-stage cp.async ring with ONE __syncthreads per k-iter
//      (iter it: wait stage it -> sync -> issue stage it+2 -> compute it).
// ---------------------------------------------------------------------------

__device__ __align__(16) float  g_q[16 * 64 * 1024];          //   4 MB
__device__ __align__(16) __half g_qth[16 * 8 * 64 * 1024];    //  16 MB
__device__ __align__(16) float  g_sc[16 * 512 * 4096];        // 128 MB
__device__ __align__(16) __half g_sch[16 * 512 * 4096];       //  64 MB
__device__ __align__(16) __half g_imgh[16 * 4096 * 1024];     // 128 MB
__device__ __align__(16) __half g_imght[16 * 1024 * 4096];    // 128 MB
__device__ __align__(16) float  g_t[16 * 8 * 64 * 1024];      //  32 MB

__device__ __forceinline__ uint32_t f2tf32(float x) {
    uint32_t r;
    asm("cvt.rna.tf32.f32 %0, %1;" : "=r"(r) : "f"(x));
    return r;
}
__device__ __forceinline__ void ldsm_x4(uint32_t& r0, uint32_t& r1,
                                        uint32_t& r2, uint32_t& r3,
                                        uint32_t addr) {
    asm volatile(
        "ldmatrix.sync.aligned.m8n8.x4.shared.b16 {%0,%1,%2,%3}, [%4];"
        : "=r"(r0), "=r"(r1), "=r"(r2), "=r"(r3) : "r"(addr));
}
__device__ __forceinline__ uint32_t h2bits(__half2 h) {
    return *reinterpret_cast<uint32_t*>(&h);
}
__device__ __forceinline__ void cp16(uint32_t dst, const void* src) {
    asm volatile("cp.async.cg.shared.global [%0], [%1], 16;"
                 :: "r"(dst), "l"(src));
}

// ======================= FP16-input NT tensor GEMM =========================
// C[M,N] = alpha * A[M,K] * B[N,K]^T, A/B fp16 row-major (K contiguous),
// fp32 accumulate. Block tile 128x128x64, 8 warps (4x2), warp 32x64, k16 mma.
// 3-stage cp.async ring, 1 barrier per iter.
static const int H16_TILE_B = 128 * 72 * 2;       // 18432 bytes per operand tile
static const int H16_STAGE = 2 * H16_TILE_B;      // 36864 bytes per stage
static const int H16_SMEM = 3 * H16_STAGE;        // 110592 bytes total

__global__ __launch_bounds__(256, 2)
void h16_gemm_nt_kernel(const __half* __restrict__ Ag,
                        const __half* __restrict__ Bg,
                        float* __restrict__ Cg,
                        int K, int lda, int ldb, int ldc,
                        long aOff, long bOff, long cOff, float alpha) {
    constexpr int ST = 72;
    extern __shared__ __align__(16) __half smh[];
    const __half* A = Ag + (long)blockIdx.z * aOff;
    const __half* B = Bg + (long)blockIdx.z * bOff;
    float* C = Cg + (long)blockIdx.z * cOff;

    const int tid = threadIdx.x;
    const int lane = tid & 31;
    const int warp = tid >> 5;
    const int g = lane >> 2;
    const int tg = lane & 3;
    const int wm = warp >> 1;     // 0..3 -> warp row * 32
    const int wn = warp & 1;      // 0..1 -> warp col * 64
    const int m0 = blockIdx.y * 128;
    const int n0 = blockIdx.x * 128;

    const uint32_t sbase = (uint32_t)__cvta_generic_to_shared(smh);

    // ldmatrix per-lane fragment offsets (within a stage)
    const int r8 = lane & 7;
    const int quad = lane >> 3;
    const int a_row = wm * 32 + ((quad & 1) << 3) + r8;
    const int a_k = (quad >> 1) << 3;
    const uint32_t a_foff = (uint32_t)(a_row * ST + a_k) * 2;
    const int b_row = wn * 64 + ((quad >> 1) << 3) + r8;
    const int b_k = (quad & 1) << 3;
    const uint32_t b_foff = (uint32_t)H16_TILE_B + (uint32_t)(b_row * ST + b_k) * 2;

    // loader lambda-ish: per-thread 4 (row, grp) pairs for A and B each
    float acc[2][8][4] = {};

    const int niter = K >> 6;   // K/64, >= 2 always here (K in {1024, 4096})

    // ---- prologue: issue stages 0 and 1 ----
    #pragma unroll
    for (int p = 0; p < 2; p++) {
        const int kt = p << 6;
        const uint32_t aoff = sbase + (uint32_t)p * (uint32_t)H16_STAGE;
        const uint32_t boff = aoff + (uint32_t)H16_TILE_B;
        #pragma unroll
        for (int i = 0; i < 4; i++) {
            int idx = tid + (i << 8);
            int row = idx >> 3;
            int grp = (idx & 7) << 3;
            cp16(aoff + (uint32_t)(row * ST + grp) * 2,
                 A + (long)(m0 + row) * lda + kt + grp);
            cp16(boff + (uint32_t)(row * ST + grp) * 2,
                 B + (long)(n0 + row) * ldb + kt + grp);
        }
        asm volatile("cp.async.commit_group;");
    }

    int stage = 0;
    for (int it = 0; it < niter; ++it) {
        // stage `it` must be resident
        if (it + 1 < niter)
            asm volatile("cp.async.wait_group 1;");
        else
            asm volatile("cp.async.wait_group 0;");
        __syncthreads();  // also guards the stage we overwrite below

        // issue loads for stage it+2 (overwrites ring slot computed at it-1)
        if (it + 2 < niter) {
            const int kt = (it + 2) << 6;
            const int sn = (stage + 2 >= 3) ? stage - 1 : stage + 2;
            const uint32_t aoff = sbase + (uint32_t)sn * (uint32_t)H16_STAGE;
            const uint32_t boff = aoff + (uint32_t)H16_TILE_B;
            #pragma unroll
            for (int i = 0; i < 4; i++) {
                int idx = tid + (i << 8);
                int row = idx >> 3;
                int grp = (idx & 7) << 3;
                cp16(aoff + (uint32_t)(row * ST + grp) * 2,
                     A + (long)(m0 + row) * lda + kt + grp);
                cp16(boff + (uint32_t)(row * ST + grp) * 2,
                     B + (long)(n0 + row) * ldb + kt + grp);
            }
            asm volatile("cp.async.commit_group;");
        }

        // ---- compute stage `it` ----
        const uint32_t stg = sbase + (uint32_t)stage * (uint32_t)H16_STAGE;
        const uint32_t a_base0 = stg + a_foff;
        const uint32_t a_base1 = a_base0 + 16 * ST * 2;
        const uint32_t b_base = stg + b_foff;

        #pragma unroll
        for (int ks = 0; ks < 4; ks++) {   // 4 x k16
            const uint32_t koff = (uint32_t)ks * 32;  // 16 halves = 32 bytes

            uint32_t af[2][4];
            ldsm_x4(af[0][0], af[0][1], af[0][2], af[0][3], a_base0 + koff);
            ldsm_x4(af[1][0], af[1][1], af[1][2], af[1][3], a_base1 + koff);

            uint32_t bf[8][2];
            #pragma unroll
            for (int nip = 0; nip < 4; nip++) {
                ldsm_x4(bf[2 * nip][0], bf[2 * nip][1],
                        bf[2 * nip + 1][0], bf[2 * nip + 1][1],
                        b_base + nip * (16 * ST * 2) + koff);
            }

            #pragma unroll
            for (int mi = 0; mi < 2; mi++)
                #pragma unroll
                for (int ni = 0; ni < 8; ni++) {
                    float* c = acc[mi][ni];
                    asm volatile(
                        "mma.sync.aligned.m16n8k16.row.col.f32.f16.f16.f32 "
                        "{%0,%1,%2,%3}, {%4,%5,%6,%7}, {%8,%9}, {%0,%1,%2,%3};"
                        : "+f"(c[0]), "+f"(c[1]), "+f"(c[2]), "+f"(c[3])
                        : "r"(af[mi][0]), "r"(af[mi][1]), "r"(af[mi][2]),
                          "r"(af[mi][3]), "r"(bf[ni][0]), "r"(bf[ni][1]));
                }
        }

        stage = (stage + 1 >= 3) ? 0 : stage + 1;
    }

    #pragma unroll
    for (int mi = 0; mi < 2; mi++) {
        int r0 = m0 + wm * 32 + mi * 16 + g;
        #pragma unroll
        for (int ni = 0; ni < 8; ni++) {
            int col = n0 + wn * 64 + ni * 8 + tg * 2;
            float2 v0 = {alpha * acc[mi][ni][0], alpha * acc[mi][ni][1]};
            float2 v1 = {alpha * acc[mi][ni][2], alpha * acc[mi][ni][3]};
            *reinterpret_cast<float2*>(C + (long)r0 * ldc + col) = v0;
            *reinterpret_cast<float2*>(C + (long)(r0 + 8) * ldc + col) = v1;
        }
    }
}

// ======================= prep: img -> fp16 + fp16 transpose ================
__global__ __launch_bounds__(256)
void prep_kernel(const float* __restrict__ img, __half* __restrict__ imgh,
                 __half* __restrict__ imght) {
    __shared__ __half tile[32][33];
    const int b = blockIdx.z;
    const int n0 = blockIdx.x * 32;
    const int c0 = blockIdx.y * 32;
    const int tx = threadIdx.x & 31;
    const int ty = threadIdx.x >> 5;
    #pragma unroll
    for (int j = 0; j < 4; j++) {
        int r = ty + j * 8;
        float v = img[((long)b * 4096 + n0 + r) * 1024 + c0 + tx];
        __half h = __float2half_rn(v);
        imgh[((long)b * 4096 + n0 + r) * 1024 + c0 + tx] = h;
        tile[r][tx] = h;
    }
    __syncthreads();
    #pragma unroll
    for (int j = 0; j < 4; j++) {
        int r = ty + j * 8;
        imght[((long)b * 1024 + c0 + r) * 4096 + n0 + tx] = tile[tx][r];
    }
}

// ======================= TF32 GEMM (step 1, NT) ============================
__global__ __launch_bounds__(256)
void tf32_gemm_nt_kernel(const float* __restrict__ A, const float* __restrict__ B,
                         float* __restrict__ C, int K, int lda, int ldb, int ldc) {
    constexpr int ST = 36;
    __shared__ uint32_t As[128 * ST];
    __shared__ uint32_t Bs[128 * ST];

    const int tid = threadIdx.x;
    const int lane = tid & 31;
    const int warp = tid >> 5;
    const int g = lane >> 2;
    const int tg = lane & 3;
    const int wm = warp >> 1;
    const int wn = warp & 1;
    const int m0 = blockIdx.y * 128;
    const int n0 = blockIdx.x * 128;

    const int r8 = lane & 7;
    const int quad = lane >> 3;
    const int a_row = wm * 32 + ((quad & 1) << 3) + r8;
    const int a_cadd = (quad >> 1) << 2;
    const uint32_t a_base0 =
        (uint32_t)__cvta_generic_to_shared(&As[a_row * ST + a_cadd]);
    const uint32_t a_base1 = a_base0 + 16 * ST * 4;
    const int b_row = wn * 64 + ((quad >> 1) << 3) + r8;
    const int b_cadd = (quad & 1) << 2;
    const uint32_t b_base =
        (uint32_t)__cvta_generic_to_shared(&Bs[b_row * ST + b_cadd]);

    float acc[2][8][4] = {};

    for (int kt = 0; kt < K; kt += 32) {
        #pragma unroll
        for (int i = 0; i < 4; i++) {
            int idx = tid + i * 256;
            int row = idx >> 3;
            int cv = (idx & 7) * 4;
            float4 va = *reinterpret_cast<const float4*>(
                A + (long)(m0 + row) * lda + kt + cv);
            uint32_t* da = &As[row * ST + cv];
            da[0] = f2tf32(va.x); da[1] = f2tf32(va.y);
            da[2] = f2tf32(va.z); da[3] = f2tf32(va.w);
            float4 vb = *reinterpret_cast<const float4*>(
                B + (long)(n0 + row) * ldb + kt + cv);
            uint32_t* db = &Bs[row * ST + cv];
            db[0] = f2tf32(vb.x); db[1] = f2tf32(vb.y);
            db[2] = f2tf32(vb.z); db[3] = f2tf32(vb.w);
        }
        __syncthreads();

        #pragma unroll
        for (int ks = 0; ks < 4; ks++) {
            const uint32_t koff = (uint32_t)ks * 32;
            uint32_t af[2][4];
            ldsm_x4(af[0][0], af[0][1], af[0][2], af[0][3], a_base0 + koff);
            ldsm_x4(af[1][0], af[1][1], af[1][2], af[1][3], a_base1 + koff);
            uint32_t bf[8][2];
            #pragma unroll
            for (int nip = 0; nip < 4; nip++) {
                ldsm_x4(bf[2 * nip][0], bf[2 * nip][1],
                        bf[2 * nip + 1][0], bf[2 * nip + 1][1],
                        b_base + nip * (16 * ST * 4) + koff);
            }
            #pragma unroll
            for (int mi = 0; mi < 2; mi++)
                #pragma unroll
                for (int ni = 0; ni < 8; ni++) {
                    float* c = acc[mi][ni];
                    asm volatile(
                        "mma.sync.aligned.m16n8k8.row.col.f32.tf32.tf32.f32 "
                        "{%0,%1,%2,%3}, {%4,%5,%6,%7}, {%8,%9}, {%0,%1,%2,%3};"
                        : "+f"(c[0]), "+f"(c[1]), "+f"(c[2]), "+f"(c[3])
                        : "r"(af[mi][0]), "r"(af[mi][1]), "r"(af[mi][2]),
                          "r"(af[mi][3]), "r"(bf[ni][0]), "r"(bf[ni][1]));
                }
        }
        __syncthreads();
    }

    #pragma unroll
    for (int mi = 0; mi < 2; mi++) {
        int r0 = m0 + wm * 32 + mi * 16 + g;
        #pragma unroll
        for (int ni = 0; ni < 8; ni++) {
            int col = n0 + wn * 64 + ni * 8 + tg * 2;
            float2 v0 = {acc[mi][ni][0], acc[mi][ni][1]};
            float2 v1 = {acc[mi][ni][2], acc[mi][ni][3]};
            *reinterpret_cast<float2*>(C + (long)r0 * ldc + col) = v0;
            *reinterpret_cast<float2*>(C + (long)(r0 + 8) * ldc + col) = v1;
        }
    }
}

// ======================= fp32 SGEMM (steps 2, 6) ===========================
template <int BM, int BN, int BK, int TM, int TN, bool TRANSB, bool OUT_HALF>
__global__ __launch_bounds__((BM / TM) * (BN / TN))
void sgemm_kernel(const float* __restrict__ Ag, const float* __restrict__ Bg,
                  void* __restrict__ Cg,
                  int M, int N, int K, int lda, int ldb, int ldc,
                  long aOff1, long aOff2, long bOff1, long bOff2,
                  long cOff1, long cOff2, int Z2, float alpha) {
    constexpr int THREADS = (BM / TM) * (BN / TN);
    const int z = blockIdx.z;
    const int z1 = z / Z2;
    const int z2 = z - z1 * Z2;
    const float* A = Ag + (long)z1 * aOff1 + (long)z2 * aOff2;
    const float* B = Bg + (long)z1 * bOff1 + (long)z2 * bOff2;

    __shared__ __align__(16) float As[BK][BM];
    __shared__ __align__(16) float Bs[BK][BN];

    const int tid = threadIdx.x;
    const int m0 = blockIdx.y * BM;
    const int n0 = blockIdx.x * BN;
    const int tm0 = (tid / (BN / TN)) * TM;
    const int tn0 = (tid % (BN / TN)) * TN;

    float acc[TM][TN] = {};

    constexpr int KV = BK / 4;
    constexpr int A_PER = (BM * KV) / THREADS;

    for (int kt = 0; kt < K; kt += BK) {
        #pragma unroll
        for (int i = 0; i < A_PER; i++) {
            int idx = tid + i * THREADS;
            int row = idx / KV;
            int cv = idx - row * KV;
            float4 v = *reinterpret_cast<const float4*>(
                A + (long)(m0 + row) * lda + kt + cv * 4);
            As[cv * 4 + 0][row] = v.x;
            As[cv * 4 + 1][row] = v.y;
            As[cv * 4 + 2][row] = v.z;
            As[cv * 4 + 3][row] = v.w;
        }
        if constexpr (TRANSB) {
            constexpr int B_PER = (BN * KV) / THREADS;
            #pragma unroll
            for (int i = 0; i < B_PER; i++) {
                int idx = tid + i * THREADS;
                int row = idx / KV;
                int cv = idx - row * KV;
                float4 v = *reinterpret_cast<const float4*>(
                    B + (long)(n0 + row) * ldb + kt + cv * 4);
                Bs[cv * 4 + 0][row] = v.x;
                Bs[cv * 4 + 1][row] = v.y;
                Bs[cv * 4 + 2][row] = v.z;
                Bs[cv * 4 + 3][row] = v.w;
            }
        } else {
            constexpr int NV = BN / 4;
            constexpr int B_PER = (BK * NV) / THREADS;
            #pragma unroll
            for (int i = 0; i < B_PER; i++) {
                int idx = tid + i * THREADS;
                int row = idx / NV;
                int cv = idx - row * NV;
                float4 v = *reinterpret_cast<const float4*>(
                    B + (long)(kt + row) * ldb + n0 + cv * 4);
                *reinterpret_cast<float4*>(&Bs[row][cv * 4]) = v;
            }
        }
        __syncthreads();

        #pragma unroll
        for (int kk = 0; kk < BK; kk++) {
            float ra[TM], rb[TN];
            #pragma unroll
            for (int i = 0; i < TM / 4; i++)
                *reinterpret_cast<float4*>(&ra[i * 4]) =
                    *reinterpret_cast<const float4*>(&As[kk][tm0 + i * 4]);
            #pragma unroll
            for (int j = 0; j < TN / 4; j++)
                *reinterpret_cast<float4*>(&rb[j * 4]) =
                    *reinterpret_cast<const float4*>(&Bs[kk][tn0 + j * 4]);
            #pragma unroll
            for (int i = 0; i < TM; i++)
                #pragma unroll
                for (int j = 0; j < TN; j++)
                    acc[i][j] = fmaf(ra[i], rb[j], acc[i][j]);
        }
        __syncthreads();
    }

    if constexpr (OUT_HALF) {
        __half* C = (__half*)Cg + (long)z1 * cOff1 + (long)z2 * cOff2;
        #pragma unroll
        for (int i = 0; i < TM; i++)
            #pragma unroll
            for (int j = 0; j < TN / 4; j++) {
                __half2 h0 = __floats2half2_rn(alpha * acc[i][j * 4 + 0],
                                               alpha * acc[i][j * 4 + 1]);
                __half2 h1 = __floats2half2_rn(alpha * acc[i][j * 4 + 2],
                                               alpha * acc[i][j * 4 + 3]);
                uint2 u = {h2bits(h0), h2bits(h1)};
                *reinterpret_cast<uint2*>(
                    C + (long)(m0 + tm0 + i) * ldc + n0 + tn0 + j * 4) = u;
            }
    } else {
        float* C = (float*)Cg + (long)z1 * cOff1 + (long)z2 * cOff2;
        #pragma unroll
        for (int i = 0; i < TM; i++)
            #pragma unroll
            for (int j = 0; j < TN / 4; j++) {
                float4 v;
                v.x = alpha * acc[i][j * 4 + 0];
                v.y = alpha * acc[i][j * 4 + 1];
                v.z = alpha * acc[i][j * 4 + 2];
                v.w = alpha * acc[i][j * 4 + 3];
                *reinterpret_cast<float4*>(
                    C + (long)(m0 + tm0 + i) * ldc + n0 + tn0 + j * 4) = v;
            }
    }
}

// ======================= softmax (fp32 in, fp16 out) =======================
__global__ __launch_bounds__(256)
void softmax4096_kernel(const float* __restrict__ S, __half* __restrict__ Sh) {
    const float* row = S + (size_t)blockIdx.x * 4096;
    __half* rowh = Sh + (size_t)blockIdx.x * 4096;
    const int tid = threadIdx.x;
    __shared__ float red[8];

    float4 v[4];
    float maxv = -3.4e38f;
    #pragma unroll
    for (int i = 0; i < 4; i++) {
        v[i] = reinterpret_cast<const float4*>(row)[tid + i * 256];
        maxv = fmaxf(maxv, fmaxf(fmaxf(v[i].x, v[i].y), fmaxf(v[i].z, v[i].w)));
    }
    #pragma unroll
    for (int o = 16; o > 0; o >>= 1)
        maxv = fmaxf(maxv, __shfl_xor_sync(0xffffffffu, maxv, o));
    if ((tid & 31) == 0) red[tid >> 5] = maxv;
    __syncthreads();
    float bm = red[0];
    #pragma unroll
    for (int i = 1; i < 8; i++) bm = fmaxf(bm, red[i]);

    float sum = 0.f;
    #pragma unroll
    for (int i = 0; i < 4; i++) {
        v[i].x = __expf(v[i].x - bm);
        v[i].y = __expf(v[i].y - bm);
        v[i].z = __expf(v[i].z - bm);
        v[i].w = __expf(v[i].w - bm);
        sum += (v[i].x + v[i].y) + (v[i].z + v[i].w);
    }
    __syncthreads();
    #pragma unroll
    for (int o = 16; o > 0; o >>= 1) sum += __shfl_xor_sync(0xffffffffu, sum, o);
    if ((tid & 31) == 0) red[tid >> 5] = sum;
    __syncthreads();
    float tot = 0.f;
    #pragma unroll
    for (int i = 0; i < 8; i++) tot += red[i];
    const float inv = 1.0f / tot;
    #pragma unroll
    for (int i = 0; i < 4; i++) {
        __half2 h0 = __floats2half2_rn(v[i].x * inv, v[i].y * inv);
        __half2 h1 = __floats2half2_rn(v[i].z * inv, v[i].w * inv);
        uint2 u = {h2bits(h0), h2bits(h1)};
        reinterpret_cast<uint2*>(rowh)[tid + i * 256] = u;
    }
}

extern "C" void kernel_launch(void* const* d_in, const int* in_sizes, int n_in,
                              void* d_out, int out_size) {
    const float* img = (const float*)d_in[0];  // (16,4096,1024)
    const float* aud = (const float*)d_in[1];  // (16,64,1024)
    const float* Wq = (const float*)d_in[2];   // (1024,1024)
    const float* Wk = (const float*)d_in[3];
    const float* Wv = (const float*)d_in[4];
    float* out = (float*)d_out;                // (16,64,1024)

    float *q, *sc, *t;
    __half *qth, *sch, *imgh, *imght;
    cudaGetSymbolAddress((void**)&q, g_q);
    cudaGetSymbolAddress((void**)&qth, g_qth);
    cudaGetSymbolAddress((void**)&sc, g_sc);
    cudaGetSymbolAddress((void**)&sch, g_sch);
    cudaGetSymbolAddress((void**)&imgh, g_imgh);
    cudaGetSymbolAddress((void**)&imght, g_imght);
    cudaGetSymbolAddress((void**)&t, g_t);

    cudaFuncSetAttribute(h16_gemm_nt_kernel,
                         cudaFuncAttributeMaxDynamicSharedMemorySize, H16_SMEM);

    const float scale = 0.08838834764831845f;  // (1024/8)^-0.5

    // 0) img -> fp16 (row-major) + fp16 transpose per batch
    prep_kernel<<<dim3(128, 32, 16), 256>>>(img, imgh, imght);

    // 1) q = aud @ Wq^T : M=1024, N=1024, K=1024 (tf32 NT) -> fp32
    tf32_gemm_nt_kernel<<<dim3(8, 8, 1), 256>>>(aud, Wq, q, 1024, 1024, 1024, 1024);

    // 2) qt_h[b,h] = Q_bh @ Wk_h : M=64, N=1024, K=128 (fp32 NN -> fp16 out)
    sgemm_kernel<64, 64, 16, 4, 4, false, true><<<dim3(16, 1, 128), 256>>>(
        q, Wk, qth, 64, 1024, 128, 1024, 1024, 1024,
        65536, 128, 0, 131072, 524288, 65536, 8, 1.0f);

    // 3) sc_b = qt_b @ img_b^T * scale : M=512, N=4096, K=1024 (fp16 NT)
    h16_gemm_nt_kernel<<<dim3(32, 4, 16), 256, H16_SMEM>>>(
        qth, imgh, sc, 1024, 1024, 1024, 4096,
        524288, 4194304, 2097152, scale);

    // 4) softmax rows (fp32 -> fp16)
    softmax4096_kernel<<<16 * 512, 256>>>(sc, sch);

    // 5) t_b = P_b @ img_b : M=512, N=1024, K=4096 (fp16 NT via img^T)
    h16_gemm_nt_kernel<<<dim3(8, 4, 16), 256, H16_SMEM>>>(
        sch, imght, t, 4096, 4096, 4096, 1024,
        2097152, 4194304, 524288, 1.0f);

    // 6) out[b,:,h*128:(h+1)*128] = t_bh @ Wv_h^T (fp32 NT)
    sgemm_kernel<64, 64, 16, 4, 4, true, false><<<dim3(2, 1, 128), 256>>>(
        t, Wv, out, 64, 128, 1024, 1024, 1024, 1024,
        524288, 65536, 0, 131072, 65536, 128, 8, 1.0f);
}

// round 16
// speedup vs baseline: 2.2856x; 1.2563x over previous
#include <cuda_runtime.h>
#include <cuda_fp16.h>
#include <cstdint>

// ---------------------------------------------------------------------------
// Cross-modal attention, aq=1, softmax=1, sigmoid=0.
// B=16, N=4096, Kq=64, C=1024, H=8, d=128. Output (16,64,1024) fp32.
//
//   0) prep: imgh = fp16(img); wvh = fp16(Wv); wkth = fp16(Wk^T)
//   1) qh   = fp16(aud @ Wq^T)      (1024x1024x1024) NT [tf32 mma]
//   2) qth  = Q_bh @ Wk_h           (64x1024x128)x128   [fp16 mma NT, M64]
//   3) sc_b = qt_b @ img_b^T * s    (512x4096x1024)x16  [fp16 mma NT]
//   4) softmax rows (fp32 -> fp16)
//   5) th_b = sc_b @ img_b          (512x1024x4096)x16  [fp16 mma NN-trans]
//   6) out  = t_bh @ Wv_h^T         (64x128x1024)x128   [fp16 mma NT, M64]
//
// R16: unified 3-stage cp.async fp16 tensor GEMM with TRANSB / OUT_HALF / M64
//      templates; img^T eliminated (NN ldmatrix.trans, validated R9);
//      steps 2 & 6 moved off fp32 sgemm onto the tensor path.
// ---------------------------------------------------------------------------

__device__ __align__(16) __half g_qh[1024 * 1024];            //   2 MB
__device__ __align__(16) __half g_qth[16 * 8 * 64 * 1024];    //  16 MB
__device__ __align__(16) float  g_sc[16 * 512 * 4096];        // 128 MB
__device__ __align__(16) __half g_sch[16 * 512 * 4096];       //  64 MB
__device__ __align__(16) __half g_imgh[16 * 4096 * 1024];     // 128 MB
__device__ __align__(16) __half g_wkth[1024 * 1024];          //   2 MB
__device__ __align__(16) __half g_wvh[1024 * 1024];           //   2 MB
__device__ __align__(16) __half g_th[16 * 8 * 64 * 1024];     //  16 MB

__device__ __forceinline__ uint32_t f2tf32(float x) {
    uint32_t r;
    asm("cvt.rna.tf32.f32 %0, %1;" : "=r"(r) : "f"(x));
    return r;
}
__device__ __forceinline__ void ldsm_x4(uint32_t& r0, uint32_t& r1,
                                        uint32_t& r2, uint32_t& r3,
                                        uint32_t addr) {
    asm volatile(
        "ldmatrix.sync.aligned.m8n8.x4.shared.b16 {%0,%1,%2,%3}, [%4];"
        : "=r"(r0), "=r"(r1), "=r"(r2), "=r"(r3) : "r"(addr));
}
__device__ __forceinline__ void ldsm_x4_t(uint32_t& r0, uint32_t& r1,
                                          uint32_t& r2, uint32_t& r3,
                                          uint32_t addr) {
    asm volatile(
        "ldmatrix.sync.aligned.m8n8.x4.trans.shared.b16 {%0,%1,%2,%3}, [%4];"
        : "=r"(r0), "=r"(r1), "=r"(r2), "=r"(r3) : "r"(addr));
}
__device__ __forceinline__ uint32_t h2bits(__half2 h) {
    return *reinterpret_cast<uint32_t*>(&h);
}
__device__ __forceinline__ void cp16(uint32_t dst, const void* src) {
    asm volatile("cp.async.cg.shared.global [%0], [%1], 16;"
                 :: "r"(dst), "l"(src));
}

// ======================= unified FP16 tensor GEMM ==========================
// C[M,N] = alpha * A[M,K] * op(B). A fp16 row-major (K contiguous).
// TRANSB: B is [N,K] (NT). else B is [K,N] (NN, via ldmatrix.trans).
// M64: only 64 valid A rows per z-slice (loads clamped, epilogue guarded).
// Block tile 128x128x64, 8 warps (4x2), warp 32x64; 3-stage cp.async ring.
template <bool TRANSB, bool OUT_HALF, bool M64>
__global__ __launch_bounds__(256, 2)
void h16_gemm_kernel(const __half* __restrict__ Ag,
                     const __half* __restrict__ Bg,
                     void* __restrict__ Cg,
                     int K, int lda, int ldb, int ldc,
                     long aOff1, long aOff2, long bOff1, long bOff2,
                     long cOff1, long cOff2, int Z2, float alpha) {
    constexpr int ST_A = 72;                 // 64 + 8 halves, 144B pitch
    constexpr int ST_B = TRANSB ? 72 : 136;  // NN: 128 + 8 halves, 272B pitch
    constexpr int A_BYTES = 128 * ST_A * 2;                    // 18432
    constexpr int B_BYTES = TRANSB ? 128 * 72 * 2 : 64 * 136 * 2;
    constexpr int STAGE = A_BYTES + B_BYTES;

    extern __shared__ __align__(16) __half smh[];
    const int z = blockIdx.z;
    const int z1 = z / Z2;
    const int z2 = z - z1 * Z2;
    const __half* A = Ag + (long)z1 * aOff1 + (long)z2 * aOff2;
    const __half* B = Bg + (long)z1 * bOff1 + (long)z2 * bOff2;

    const int tid = threadIdx.x;
    const int lane = tid & 31;
    const int warp = tid >> 5;
    const int g = lane >> 2;
    const int tg = lane & 3;
    const int wm = warp >> 1;     // 0..3 -> warp row * 32
    const int wn = warp & 1;      // 0..1 -> warp col * 64
    const int m0 = blockIdx.y * 128;
    const int n0 = blockIdx.x * 128;

    const uint32_t sbase = (uint32_t)__cvta_generic_to_shared(smh);

    // fragment offsets within a stage
    const int r8 = lane & 7;
    const int quad = lane >> 3;
    const int a_row = wm * 32 + ((quad & 1) << 3) + r8;
    const int a_k = (quad >> 1) << 3;
    const uint32_t a_foff = (uint32_t)(a_row * ST_A + a_k) * 2;
    uint32_t b_foff;
    if constexpr (TRANSB) {
        const int b_row = wn * 64 + ((quad >> 1) << 3) + r8;
        const int b_k = (quad & 1) << 3;
        b_foff = (uint32_t)A_BYTES + (uint32_t)(b_row * ST_B + b_k) * 2;
    } else {
        const int b_krow = ((quad & 1) << 3) + r8;
        const int b_n = wn * 64 + ((quad >> 1) << 3);
        b_foff = (uint32_t)A_BYTES + (uint32_t)(b_krow * ST_B + b_n) * 2;
    }

    float acc[2][8][4] = {};
    const int niter = K >> 6;

    // loader helper (macro-ish via lambda)
    auto issue_stage = [&](int st, int kt) {
        const uint32_t aoff = sbase + (uint32_t)st * (uint32_t)STAGE;
        const uint32_t boff = aoff + (uint32_t)A_BYTES;
        #pragma unroll
        for (int i = 0; i < 4; i++) {
            int idx = tid + (i << 8);
            int row = idx >> 3;
            int grp = (idx & 7) << 3;
            int rowc = M64 ? (row & 63) : row;
            cp16(aoff + (uint32_t)(row * ST_A + grp) * 2,
                 A + (long)(m0 + rowc) * lda + kt + grp);
        }
        if constexpr (TRANSB) {
            #pragma unroll
            for (int i = 0; i < 4; i++) {
                int idx = tid + (i << 8);
                int row = idx >> 3;
                int grp = (idx & 7) << 3;
                cp16(boff + (uint32_t)(row * ST_B + grp) * 2,
                     B + (long)(n0 + row) * ldb + kt + grp);
            }
        } else {
            #pragma unroll
            for (int i = 0; i < 4; i++) {
                int idx = tid + (i << 8);
                int krow = idx >> 4;          // 0..63
                int cv = (idx & 15) << 3;     // 0..120
                cp16(boff + (uint32_t)(krow * ST_B + cv) * 2,
                     B + (long)(kt + krow) * ldb + n0 + cv);
            }
        }
        asm volatile("cp.async.commit_group;");
    };

    // prologue: stages 0, 1
    issue_stage(0, 0);
    if (niter > 1) issue_stage(1, 64);

    int stage = 0;
    for (int it = 0; it < niter; ++it) {
        if (it + 1 < niter)
            asm volatile("cp.async.wait_group 1;");
        else
            asm volatile("cp.async.wait_group 0;");
        __syncthreads();

        if (it + 2 < niter) {
            const int sn = (stage + 2 >= 3) ? stage - 1 : stage + 2;
            issue_stage(sn, (it + 2) << 6);
        }

        const uint32_t stg = sbase + (uint32_t)stage * (uint32_t)STAGE;
        const uint32_t a_base0 = stg + a_foff;
        const uint32_t a_base1 = a_base0 + 16 * ST_A * 2;
        const uint32_t b_base = stg + b_foff;

        #pragma unroll
        for (int ks = 0; ks < 4; ks++) {
            const uint32_t koff = (uint32_t)ks * 32;

            uint32_t af[2][4];
            ldsm_x4(af[0][0], af[0][1], af[0][2], af[0][3], a_base0 + koff);
            ldsm_x4(af[1][0], af[1][1], af[1][2], af[1][3], a_base1 + koff);

            uint32_t bf[8][2];
            if constexpr (TRANSB) {
                #pragma unroll
                for (int nip = 0; nip < 4; nip++) {
                    ldsm_x4(bf[2 * nip][0], bf[2 * nip][1],
                            bf[2 * nip + 1][0], bf[2 * nip + 1][1],
                            b_base + nip * (16 * ST_B * 2) + koff);
                }
            } else {
                const uint32_t krow_off = (uint32_t)ks * 16 * ST_B * 2;
                #pragma unroll
                for (int nip = 0; nip < 4; nip++) {
                    ldsm_x4_t(bf[2 * nip][0], bf[2 * nip][1],
                              bf[2 * nip + 1][0], bf[2 * nip + 1][1],
                              b_base + krow_off + nip * (16 * 2));
                }
            }

            #pragma unroll
            for (int mi = 0; mi < 2; mi++)
                #pragma unroll
                for (int ni = 0; ni < 8; ni++) {
                    float* c = acc[mi][ni];
                    asm volatile(
                        "mma.sync.aligned.m16n8k16.row.col.f32.f16.f16.f32 "
                        "{%0,%1,%2,%3}, {%4,%5,%6,%7}, {%8,%9}, {%0,%1,%2,%3};"
                        : "+f"(c[0]), "+f"(c[1]), "+f"(c[2]), "+f"(c[3])
                        : "r"(af[mi][0]), "r"(af[mi][1]), "r"(af[mi][2]),
                          "r"(af[mi][3]), "r"(bf[ni][0]), "r"(bf[ni][1]));
                }
        }
        stage = (stage + 1 >= 3) ? 0 : stage + 1;
    }

    // ---- epilogue ----
    #pragma unroll
    for (int mi = 0; mi < 2; mi++) {
        const int rbase = wm * 32 + mi * 16;
        if (M64 && rbase >= 64) continue;
        const int r0 = m0 + rbase + g;
        #pragma unroll
        for (int ni = 0; ni < 8; ni++) {
            int col = n0 + wn * 64 + ni * 8 + tg * 2;
            if constexpr (OUT_HALF) {
                __half* C = (__half*)Cg + (long)z1 * cOff1 + (long)z2 * cOff2;
                __half2 h0 = __floats2half2_rn(alpha * acc[mi][ni][0],
                                               alpha * acc[mi][ni][1]);
                __half2 h1 = __floats2half2_rn(alpha * acc[mi][ni][2],
                                               alpha * acc[mi][ni][3]);
                *reinterpret_cast<__half2*>(C + (long)r0 * ldc + col) = h0;
                *reinterpret_cast<__half2*>(C + (long)(r0 + 8) * ldc + col) = h1;
            } else {
                float* C = (float*)Cg + (long)z1 * cOff1 + (long)z2 * cOff2;
                float2 v0 = {alpha * acc[mi][ni][0], alpha * acc[mi][ni][1]};
                float2 v1 = {alpha * acc[mi][ni][2], alpha * acc[mi][ni][3]};
                *reinterpret_cast<float2*>(C + (long)r0 * ldc + col) = v0;
                *reinterpret_cast<float2*>(C + (long)(r0 + 8) * ldc + col) = v1;
            }
        }
    }
}

static const int SM_H16_NT = 3 * (128 * 72 * 2 + 128 * 72 * 2);  // 110592
static const int SM_H16_NN = 3 * (128 * 72 * 2 + 64 * 136 * 2);  // 107520

// ======================= prep kernels ======================================
__global__ __launch_bounds__(256)
void cast_f2h_kernel(const float* __restrict__ src, __half* __restrict__ dst,
                     int n4) {
    int i = blockIdx.x * 256 + threadIdx.x;
    const int stride = gridDim.x * 256;
    for (; i < n4; i += stride) {
        float4 v = reinterpret_cast<const float4*>(src)[i];
        __half2 h0 = __floats2half2_rn(v.x, v.y);
        __half2 h1 = __floats2half2_rn(v.z, v.w);
        uint2 u = {h2bits(h0), h2bits(h1)};
        reinterpret_cast<uint2*>(dst)[i] = u;
    }
}

__global__ __launch_bounds__(256)
void transpose_f2h_kernel(const float* __restrict__ src,
                          __half* __restrict__ dst) {
    __shared__ __half tile[32][33];
    const int r0 = blockIdx.y * 32;
    const int c0 = blockIdx.x * 32;
    const int tx = threadIdx.x & 31;
    const int ty = threadIdx.x >> 5;
    #pragma unroll
    for (int j = 0; j < 4; j++) {
        int r = ty + j * 8;
        tile[r][tx] = __float2half_rn(src[(r0 + r) * 1024 + c0 + tx]);
    }
    __syncthreads();
    #pragma unroll
    for (int j = 0; j < 4; j++) {
        int r = ty + j * 8;
        dst[(long)(c0 + r) * 1024 + r0 + tx] = tile[tx][r];
    }
}

// ======================= TF32 GEMM (step 1, NT, fp16 out) ==================
__global__ __launch_bounds__(256)
void tf32_gemm_nt_kernel(const float* __restrict__ A, const float* __restrict__ B,
                         __half* __restrict__ C, int K, int lda, int ldb, int ldc) {
    constexpr int ST = 36;
    __shared__ uint32_t As[128 * ST];
    __shared__ uint32_t Bs[128 * ST];

    const int tid = threadIdx.x;
    const int lane = tid & 31;
    const int warp = tid >> 5;
    const int g = lane >> 2;
    const int tg = lane & 3;
    const int wm = warp >> 1;
    const int wn = warp & 1;
    const int m0 = blockIdx.y * 128;
    const int n0 = blockIdx.x * 128;

    const int r8 = lane & 7;
    const int quad = lane >> 3;
    const int a_row = wm * 32 + ((quad & 1) << 3) + r8;
    const int a_cadd = (quad >> 1) << 2;
    const uint32_t a_base0 =
        (uint32_t)__cvta_generic_to_shared(&As[a_row * ST + a_cadd]);
    const uint32_t a_base1 = a_base0 + 16 * ST * 4;
    const int b_row = wn * 64 + ((quad >> 1) << 3) + r8;
    const int b_cadd = (quad & 1) << 2;
    const uint32_t b_base =
        (uint32_t)__cvta_generic_to_shared(&Bs[b_row * ST + b_cadd]);

    float acc[2][8][4] = {};

    for (int kt = 0; kt < K; kt += 32) {
        #pragma unroll
        for (int i = 0; i < 4; i++) {
            int idx = tid + i * 256;
            int row = idx >> 3;
            int cv = (idx & 7) * 4;
            float4 va = *reinterpret_cast<const float4*>(
                A + (long)(m0 + row) * lda + kt + cv);
            uint32_t* da = &As[row * ST + cv];
            da[0] = f2tf32(va.x); da[1] = f2tf32(va.y);
            da[2] = f2tf32(va.z); da[3] = f2tf32(va.w);
            float4 vb = *reinterpret_cast<const float4*>(
                B + (long)(n0 + row) * ldb + kt + cv);
            uint32_t* db = &Bs[row * ST + cv];
            db[0] = f2tf32(vb.x); db[1] = f2tf32(vb.y);
            db[2] = f2tf32(vb.z); db[3] = f2tf32(vb.w);
        }
        __syncthreads();

        #pragma unroll
        for (int ks = 0; ks < 4; ks++) {
            const uint32_t koff = (uint32_t)ks * 32;
            uint32_t af[2][4];
            ldsm_x4(af[0][0], af[0][1], af[0][2], af[0][3], a_base0 + koff);
            ldsm_x4(af[1][0], af[1][1], af[1][2], af[1][3], a_base1 + koff);
            uint32_t bf[8][2];
            #pragma unroll
            for (int nip = 0; nip < 4; nip++) {
                ldsm_x4(bf[2 * nip][0], bf[2 * nip][1],
                        bf[2 * nip + 1][0], bf[2 * nip + 1][1],
                        b_base + nip * (16 * ST * 4) + koff);
            }
            #pragma unroll
            for (int mi = 0; mi < 2; mi++)
                #pragma unroll
                for (int ni = 0; ni < 8; ni++) {
                    float* c = acc[mi][ni];
                    asm volatile(
                        "mma.sync.aligned.m16n8k8.row.col.f32.tf32.tf32.f32 "
                        "{%0,%1,%2,%3}, {%4,%5,%6,%7}, {%8,%9}, {%0,%1,%2,%3};"
                        : "+f"(c[0]), "+f"(c[1]), "+f"(c[2]), "+f"(c[3])
                        : "r"(af[mi][0]), "r"(af[mi][1]), "r"(af[mi][2]),
                          "r"(af[mi][3]), "r"(bf[ni][0]), "r"(bf[ni][1]));
                }
        }
        __syncthreads();
    }

    #pragma unroll
    for (int mi = 0; mi < 2; mi++) {
        int r0 = m0 + wm * 32 + mi * 16 + g;
        #pragma unroll
        for (int ni = 0; ni < 8; ni++) {
            int col = n0 + wn * 64 + ni * 8 + tg * 2;
            __half2 h0 = __floats2half2_rn(acc[mi][ni][0], acc[mi][ni][1]);
            __half2 h1 = __floats2half2_rn(acc[mi][ni][2], acc[mi][ni][3]);
            *reinterpret_cast<__half2*>(C + (long)r0 * ldc + col) = h0;
            *reinterpret_cast<__half2*>(C + (long)(r0 + 8) * ldc + col) = h1;
        }
    }
}

// ======================= softmax (fp32 in, fp16 out) =======================
__global__ __launch_bounds__(256)
void softmax4096_kernel(const float* __restrict__ S, __half* __restrict__ Sh) {
    const float* row = S + (size_t)blockIdx.x * 4096;
    __half* rowh = Sh + (size_t)blockIdx.x * 4096;
    const int tid = threadIdx.x;
    __shared__ float red[8];

    float4 v[4];
    float maxv = -3.4e38f;
    #pragma unroll
    for (int i = 0; i < 4; i++) {
        v[i] = reinterpret_cast<const float4*>(row)[tid + i * 256];
        maxv = fmaxf(maxv, fmaxf(fmaxf(v[i].x, v[i].y), fmaxf(v[i].z, v[i].w)));
    }
    #pragma unroll
    for (int o = 16; o > 0; o >>= 1)
        maxv = fmaxf(maxv, __shfl_xor_sync(0xffffffffu, maxv, o));
    if ((tid & 31) == 0) red[tid >> 5] = maxv;
    __syncthreads();
    float bm = red[0];
    #pragma unroll
    for (int i = 1; i < 8; i++) bm = fmaxf(bm, red[i]);

    float sum = 0.f;
    #pragma unroll
    for (int i = 0; i < 4; i++) {
        v[i].x = __expf(v[i].x - bm);
        v[i].y = __expf(v[i].y - bm);
        v[i].z = __expf(v[i].z - bm);
        v[i].w = __expf(v[i].w - bm);
        sum += (v[i].x + v[i].y) + (v[i].z + v[i].w);
    }
    __syncthreads();
    #pragma unroll
    for (int o = 16; o > 0; o >>= 1) sum += __shfl_xor_sync(0xffffffffu, sum, o);
    if ((tid & 31) == 0) red[tid >> 5] = sum;
    __syncthreads();
    float tot = 0.f;
    #pragma unroll
    for (int i = 0; i < 8; i++) tot += red[i];
    const float inv = 1.0f / tot;
    #pragma unroll
    for (int i = 0; i < 4; i++) {
        __half2 h0 = __floats2half2_rn(v[i].x * inv, v[i].y * inv);
        __half2 h1 = __floats2half2_rn(v[i].z * inv, v[i].w * inv);
        uint2 u = {h2bits(h0), h2bits(h1)};
        reinterpret_cast<uint2*>(rowh)[tid + i * 256] = u;
    }
}

extern "C" void kernel_launch(void* const* d_in, const int* in_sizes, int n_in,
                              void* d_out, int out_size) {
    const float* img = (const float*)d_in[0];  // (16,4096,1024)
    const float* aud = (const float*)d_in[1];  // (16,64,1024)
    const float* Wq = (const float*)d_in[2];   // (1024,1024)
    const float* Wk = (const float*)d_in[3];
    const float* Wv = (const float*)d_in[4];
    float* out = (float*)d_out;                // (16,64,1024)

    float* sc;
    __half *qh, *qth, *sch, *imgh, *wkth, *wvh, *th;
    cudaGetSymbolAddress((void**)&qh, g_qh);
    cudaGetSymbolAddress((void**)&qth, g_qth);
    cudaGetSymbolAddress((void**)&sc, g_sc);
    cudaGetSymbolAddress((void**)&sch, g_sch);
    cudaGetSymbolAddress((void**)&imgh, g_imgh);
    cudaGetSymbolAddress((void**)&wkth, g_wkth);
    cudaGetSymbolAddress((void**)&wvh, g_wvh);
    cudaGetSymbolAddress((void**)&th, g_th);

    cudaFuncSetAttribute(h16_gemm_kernel<true, false, false>,
                         cudaFuncAttributeMaxDynamicSharedMemorySize, SM_H16_NT);
    cudaFuncSetAttribute(h16_gemm_kernel<false, true, false>,
                         cudaFuncAttributeMaxDynamicSharedMemorySize, SM_H16_NN);
    cudaFuncSetAttribute(h16_gemm_kernel<true, true, true>,
                         cudaFuncAttributeMaxDynamicSharedMemorySize, SM_H16_NT);
    cudaFuncSetAttribute(h16_gemm_kernel<true, false, true>,
                         cudaFuncAttributeMaxDynamicSharedMemorySize, SM_H16_NT);

    const float scale = 0.08838834764831845f;  // (1024/8)^-0.5

    // 0) casts + Wk transpose
    cast_f2h_kernel<<<16384, 256>>>(img, imgh, 16 * 4096 * 1024 / 4);
    cast_f2h_kernel<<<1024, 256>>>(Wv, wvh, 1024 * 1024 / 4);
    transpose_f2h_kernel<<<dim3(32, 32), 256>>>(Wk, wkth);

    // 1) qh = fp16(aud @ Wq^T) : M=1024, N=1024, K=1024 (tf32 NT)
    tf32_gemm_nt_kernel<<<dim3(8, 8, 1), 256>>>(aud, Wq, qh, 1024, 1024, 1024, 1024);

    // 2) qth[b,h] = Q_bh @ Wk_h : M=64(M64), N=1024, K=128; z=b*8+h
    h16_gemm_kernel<true, true, true><<<dim3(8, 1, 128), 256, SM_H16_NT>>>(
        qh, wkth, qth, 128, 1024, 1024, 1024,
        65536, 128, 0, 128, 524288, 65536, 8, 1.0f);

    // 3) sc_b = qt_b @ img_b^T * scale : M=512, N=4096, K=1024 (NT)
    h16_gemm_kernel<true, false, false><<<dim3(32, 4, 16), 256, SM_H16_NT>>>(
        qth, imgh, sc, 1024, 1024, 1024, 4096,
        524288, 0, 4194304, 0, 2097152, 0, 1, scale);

    // 4) softmax rows (fp32 -> fp16)
    softmax4096_kernel<<<16 * 512, 256>>>(sc, sch);

    // 5) th_b = P_b @ img_b : M=512, N=1024, K=4096 (NN via ldmatrix.trans)
    h16_gemm_kernel<false, true, false><<<dim3(8, 4, 16), 256, SM_H16_NN>>>(
        sch, imgh, th, 4096, 4096, 1024, 1024,
        2097152, 0, 4194304, 0, 524288, 0, 1, 1.0f);

    // 6) out[b,:,hd:hd+128] = t_bh @ Wv_h^T : M=64(M64), N=128, K=1024; z=b*8+h
    h16_gemm_kernel<true, false, true><<<dim3(1, 1, 128), 256, SM_H16_NT>>>(
        th, wvh, out, 1024, 1024, 1024, 1024,
        524288, 65536, 0, 131072, 65536, 128, 8, 1.0f);
}

// round 17
// speedup vs baseline: 2.5001x; 1.0939x over previous
#include <cuda_runtime.h>
#include <cuda_fp16.h>
#include <cstdint>

// ---------------------------------------------------------------------------
// Cross-modal attention, aq=1, softmax=1, sigmoid=0.
// B=16, N=4096, Kq=64, C=1024, H=8, d=128. Output (16,64,1024) fp32.
//
//   0) prep: imgh=fp16(img); audh=fp16(aud); wqh=fp16(Wq); wvh=fp16(Wv);
//            wkth=fp16(Wk^T)
//   1) qh   = audh @ wqh^T          (1024x1024x1024)    [fp16 mma NT]
//   2) qth  = Q_bh @ Wk_h           (64x1024x128)x128   [fp16 mma NT, M64]
//   3) sch  = qt_b @ img_b^T * s    (512x4096x1024)x16  [fp16 mma NT, fp16 out]
//   4) softmax rows, fp16 in-place
//   5) th_b = sch_b @ img_b         (512x1024x4096)x16  [fp16 mma NN-trans]
//   6) out  = t_bh @ Wv_h^T         (64x128x1024)x128   [fp16 mma NT, M64]
// ---------------------------------------------------------------------------

__device__ __align__(16) __half g_qh[1024 * 1024];            //   2 MB
__device__ __align__(16) __half g_qth[16 * 8 * 64 * 1024];    //  16 MB
__device__ __align__(16) __half g_sch[16 * 512 * 4096];       //  64 MB
__device__ __align__(16) __half g_imgh[16 * 4096 * 1024];     // 128 MB
__device__ __align__(16) __half g_audh[16 * 64 * 1024];       //   2 MB
__device__ __align__(16) __half g_wqh[1024 * 1024];           //   2 MB
__device__ __align__(16) __half g_wkth[1024 * 1024];          //   2 MB
__device__ __align__(16) __half g_wvh[1024 * 1024];           //   2 MB
__device__ __align__(16) __half g_th[16 * 8 * 64 * 1024];     //  16 MB

__device__ __forceinline__ void ldsm_x4(uint32_t& r0, uint32_t& r1,
                                        uint32_t& r2, uint32_t& r3,
                                        uint32_t addr) {
    asm volatile(
        "ldmatrix.sync.aligned.m8n8.x4.shared.b16 {%0,%1,%2,%3}, [%4];"
        : "=r"(r0), "=r"(r1), "=r"(r2), "=r"(r3) : "r"(addr));
}
__device__ __forceinline__ void ldsm_x4_t(uint32_t& r0, uint32_t& r1,
                                          uint32_t& r2, uint32_t& r3,
                                          uint32_t addr) {
    asm volatile(
        "ldmatrix.sync.aligned.m8n8.x4.trans.shared.b16 {%0,%1,%2,%3}, [%4];"
        : "=r"(r0), "=r"(r1), "=r"(r2), "=r"(r3) : "r"(addr));
}
__device__ __forceinline__ uint32_t h2bits(__half2 h) {
    return *reinterpret_cast<uint32_t*>(&h);
}
__device__ __forceinline__ void cp16(uint32_t dst, const void* src) {
    asm volatile("cp.async.cg.shared.global [%0], [%1], 16;"
                 :: "r"(dst), "l"(src));
}

// ======================= unified FP16 tensor GEMM ==========================
// C[M,N] = alpha * A[M,K] * op(B). A fp16 row-major (K contiguous).
// TRANSB: B is [N,K] (NT). else B is [K,N] (NN, via ldmatrix.trans).
// M64: only 64 valid A rows per z-slice (loads clamped, epilogue guarded).
// Block tile 128x128x64, 8 warps (4x2), warp 32x64; 3-stage cp.async ring.
template <bool TRANSB, bool OUT_HALF, bool M64>
__global__ __launch_bounds__(256, 2)
void h16_gemm_kernel(const __half* __restrict__ Ag,
                     const __half* __restrict__ Bg,
                     void* __restrict__ Cg,
                     int K, int lda, int ldb, int ldc,
                     long aOff1, long aOff2, long bOff1, long bOff2,
                     long cOff1, long cOff2, int Z2, float alpha) {
    constexpr int ST_A = 72;
    constexpr int ST_B = TRANSB ? 72 : 136;
    constexpr int A_BYTES = 128 * ST_A * 2;
    constexpr int B_BYTES = TRANSB ? 128 * 72 * 2 : 64 * 136 * 2;
    constexpr int STAGE = A_BYTES + B_BYTES;

    extern __shared__ __align__(16) __half smh[];
    const int z = blockIdx.z;
    const int z1 = z / Z2;
    const int z2 = z - z1 * Z2;
    const __half* A = Ag + (long)z1 * aOff1 + (long)z2 * aOff2;
    const __half* B = Bg + (long)z1 * bOff1 + (long)z2 * bOff2;

    const int tid = threadIdx.x;
    const int lane = tid & 31;
    const int warp = tid >> 5;
    const int g = lane >> 2;
    const int tg = lane & 3;
    const int wm = warp >> 1;
    const int wn = warp & 1;
    const int m0 = blockIdx.y * 128;
    const int n0 = blockIdx.x * 128;

    const uint32_t sbase = (uint32_t)__cvta_generic_to_shared(smh);

    const int r8 = lane & 7;
    const int quad = lane >> 3;
    const int a_row = wm * 32 + ((quad & 1) << 3) + r8;
    const int a_k = (quad >> 1) << 3;
    const uint32_t a_foff = (uint32_t)(a_row * ST_A + a_k) * 2;
    uint32_t b_foff;
    if constexpr (TRANSB) {
        const int b_row = wn * 64 + ((quad >> 1) << 3) + r8;
        const int b_k = (quad & 1) << 3;
        b_foff = (uint32_t)A_BYTES + (uint32_t)(b_row * ST_B + b_k) * 2;
    } else {
        const int b_krow = ((quad & 1) << 3) + r8;
        const int b_n = wn * 64 + ((quad >> 1) << 3);
        b_foff = (uint32_t)A_BYTES + (uint32_t)(b_krow * ST_B + b_n) * 2;
    }

    float acc[2][8][4] = {};
    const int niter = K >> 6;

    auto issue_stage = [&](int st, int kt) {
        const uint32_t aoff = sbase + (uint32_t)st * (uint32_t)STAGE;
        const uint32_t boff = aoff + (uint32_t)A_BYTES;
        #pragma unroll
        for (int i = 0; i < 4; i++) {
            int idx = tid + (i << 8);
            int row = idx >> 3;
            int grp = (idx & 7) << 3;
            int rowc = M64 ? (row & 63) : row;
            cp16(aoff + (uint32_t)(row * ST_A + grp) * 2,
                 A + (long)(m0 + rowc) * lda + kt + grp);
        }
        if constexpr (TRANSB) {
            #pragma unroll
            for (int i = 0; i < 4; i++) {
                int idx = tid + (i << 8);
                int row = idx >> 3;
                int grp = (idx & 7) << 3;
                cp16(boff + (uint32_t)(row * ST_B + grp) * 2,
                     B + (long)(n0 + row) * ldb + kt + grp);
            }
        } else {
            #pragma unroll
            for (int i = 0; i < 4; i++) {
                int idx = tid + (i << 8);
                int krow = idx >> 4;
                int cv = (idx & 15) << 3;
                cp16(boff + (uint32_t)(krow * ST_B + cv) * 2,
                     B + (long)(kt + krow) * ldb + n0 + cv);
            }
        }
        asm volatile("cp.async.commit_group;");
    };

    issue_stage(0, 0);
    if (niter > 1) issue_stage(1, 64);

    int stage = 0;
    for (int it = 0; it < niter; ++it) {
        if (it + 1 < niter)
            asm volatile("cp.async.wait_group 1;");
        else
            asm volatile("cp.async.wait_group 0;");
        __syncthreads();

        if (it + 2 < niter) {
            const int sn = (stage + 2 >= 3) ? stage - 1 : stage + 2;
            issue_stage(sn, (it + 2) << 6);
        }

        const uint32_t stg = sbase + (uint32_t)stage * (uint32_t)STAGE;
        const uint32_t a_base0 = stg + a_foff;
        const uint32_t a_base1 = a_base0 + 16 * ST_A * 2;
        const uint32_t b_base = stg + b_foff;

        #pragma unroll
        for (int ks = 0; ks < 4; ks++) {
            const uint32_t koff = (uint32_t)ks * 32;

            uint32_t af[2][4];
            ldsm_x4(af[0][0], af[0][1], af[0][2], af[0][3], a_base0 + koff);
            ldsm_x4(af[1][0], af[1][1], af[1][2], af[1][3], a_base1 + koff);

            uint32_t bf[8][2];
            if constexpr (TRANSB) {
                #pragma unroll
                for (int nip = 0; nip < 4; nip++) {
                    ldsm_x4(bf[2 * nip][0], bf[2 * nip][1],
                            bf[2 * nip + 1][0], bf[2 * nip + 1][1],
                            b_base + nip * (16 * ST_B * 2) + koff);
                }
            } else {
                const uint32_t krow_off = (uint32_t)ks * 16 * ST_B * 2;
                #pragma unroll
                for (int nip = 0; nip < 4; nip++) {
                    ldsm_x4_t(bf[2 * nip][0], bf[2 * nip][1],
                              bf[2 * nip + 1][0], bf[2 * nip + 1][1],
                              b_base + krow_off + nip * (16 * 2));
                }
            }

            #pragma unroll
            for (int mi = 0; mi < 2; mi++)
                #pragma unroll
                for (int ni = 0; ni < 8; ni++) {
                    float* c = acc[mi][ni];
                    asm volatile(
                        "mma.sync.aligned.m16n8k16.row.col.f32.f16.f16.f32 "
                        "{%0,%1,%2,%3}, {%4,%5,%6,%7}, {%8,%9}, {%0,%1,%2,%3};"
                        : "+f"(c[0]), "+f"(c[1]), "+f"(c[2]), "+f"(c[3])
                        : "r"(af[mi][0]), "r"(af[mi][1]), "r"(af[mi][2]),
                          "r"(af[mi][3]), "r"(bf[ni][0]), "r"(bf[ni][1]));
                }
        }
        stage = (stage + 1 >= 3) ? 0 : stage + 1;
    }

    #pragma unroll
    for (int mi = 0; mi < 2; mi++) {
        const int rbase = wm * 32 + mi * 16;
        if (M64 && rbase >= 64) continue;
        const int r0 = m0 + rbase + g;
        #pragma unroll
        for (int ni = 0; ni < 8; ni++) {
            int col = n0 + wn * 64 + ni * 8 + tg * 2;
            if constexpr (OUT_HALF) {
                __half* C = (__half*)Cg + (long)z1 * cOff1 + (long)z2 * cOff2;
                __half2 h0 = __floats2half2_rn(alpha * acc[mi][ni][0],
                                               alpha * acc[mi][ni][1]);
                __half2 h1 = __floats2half2_rn(alpha * acc[mi][ni][2],
                                               alpha * acc[mi][ni][3]);
                *reinterpret_cast<__half2*>(C + (long)r0 * ldc + col) = h0;
                *reinterpret_cast<__half2*>(C + (long)(r0 + 8) * ldc + col) = h1;
            } else {
                float* C = (float*)Cg + (long)z1 * cOff1 + (long)z2 * cOff2;
                float2 v0 = {alpha * acc[mi][ni][0], alpha * acc[mi][ni][1]};
                float2 v1 = {alpha * acc[mi][ni][2], alpha * acc[mi][ni][3]};
                *reinterpret_cast<float2*>(C + (long)r0 * ldc + col) = v0;
                *reinterpret_cast<float2*>(C + (long)(r0 + 8) * ldc + col) = v1;
            }
        }
    }
}

static const int SM_H16_NT = 3 * (128 * 72 * 2 + 128 * 72 * 2);  // 110592
static const int SM_H16_NN = 3 * (128 * 72 * 2 + 64 * 136 * 2);  // 107520

// ======================= prep kernels ======================================
__global__ __launch_bounds__(256)
void cast_f2h_kernel(const float* __restrict__ src, __half* __restrict__ dst,
                     int n4) {
    int i = blockIdx.x * 256 + threadIdx.x;
    const int stride = gridDim.x * 256;
    for (; i < n4; i += stride) {
        float4 v = reinterpret_cast<const float4*>(src)[i];
        __half2 h0 = __floats2half2_rn(v.x, v.y);
        __half2 h1 = __floats2half2_rn(v.z, v.w);
        uint2 u = {h2bits(h0), h2bits(h1)};
        reinterpret_cast<uint2*>(dst)[i] = u;
    }
}

__global__ __launch_bounds__(256)
void transpose_f2h_kernel(const float* __restrict__ src,
                          __half* __restrict__ dst) {
    __shared__ __half tile[32][33];
    const int r0 = blockIdx.y * 32;
    const int c0 = blockIdx.x * 32;
    const int tx = threadIdx.x & 31;
    const int ty = threadIdx.x >> 5;
    #pragma unroll
    for (int j = 0; j < 4; j++) {
        int r = ty + j * 8;
        tile[r][tx] = __float2half_rn(src[(r0 + r) * 1024 + c0 + tx]);
    }
    __syncthreads();
    #pragma unroll
    for (int j = 0; j < 4; j++) {
        int r = ty + j * 8;
        dst[(long)(c0 + r) * 1024 + r0 + tx] = tile[tx][r];
    }
}

// ======================= softmax (fp16 in-place) ===========================
__global__ __launch_bounds__(256)
void softmax4096_h_kernel(__half* __restrict__ Sh) {
    __half* row = Sh + (size_t)blockIdx.x * 4096;
    const int tid = threadIdx.x;
    __shared__ float red[8];

    // 16 halves per thread as 4 x uint2 (8B) loads
    float v[16];
    float maxv = -3.4e38f;
    #pragma unroll
    for (int i = 0; i < 4; i++) {
        uint2 u = reinterpret_cast<const uint2*>(row)[tid + i * 256];
        __half2 h0 = *reinterpret_cast<__half2*>(&u.x);
        __half2 h1 = *reinterpret_cast<__half2*>(&u.y);
        float2 f0 = __half22float2(h0);
        float2 f1 = __half22float2(h1);
        v[i * 4 + 0] = f0.x; v[i * 4 + 1] = f0.y;
        v[i * 4 + 2] = f1.x; v[i * 4 + 3] = f1.y;
        maxv = fmaxf(maxv, fmaxf(fmaxf(f0.x, f0.y), fmaxf(f1.x, f1.y)));
    }
    #pragma unroll
    for (int o = 16; o > 0; o >>= 1)
        maxv = fmaxf(maxv, __shfl_xor_sync(0xffffffffu, maxv, o));
    if ((tid & 31) == 0) red[tid >> 5] = maxv;
    __syncthreads();
    float bm = red[0];
    #pragma unroll
    for (int i = 1; i < 8; i++) bm = fmaxf(bm, red[i]);

    float sum = 0.f;
    #pragma unroll
    for (int i = 0; i < 16; i++) {
        v[i] = __expf(v[i] - bm);
        sum += v[i];
    }
    __syncthreads();
    #pragma unroll
    for (int o = 16; o > 0; o >>= 1) sum += __shfl_xor_sync(0xffffffffu, sum, o);
    if ((tid & 31) == 0) red[tid >> 5] = sum;
    __syncthreads();
    float tot = 0.f;
    #pragma unroll
    for (int i = 0; i < 8; i++) tot += red[i];
    const float inv = 1.0f / tot;

    #pragma unroll
    for (int i = 0; i < 4; i++) {
        __half2 h0 = __floats2half2_rn(v[i * 4 + 0] * inv, v[i * 4 + 1] * inv);
        __half2 h1 = __floats2half2_rn(v[i * 4 + 2] * inv, v[i * 4 + 3] * inv);
        uint2 u = {h2bits(h0), h2bits(h1)};
        reinterpret_cast<uint2*>(row)[tid + i * 256] = u;
    }
}

extern "C" void kernel_launch(void* const* d_in, const int* in_sizes, int n_in,
                              void* d_out, int out_size) {
    const float* img = (const float*)d_in[0];  // (16,4096,1024)
    const float* aud = (const float*)d_in[1];  // (16,64,1024)
    const float* Wq = (const float*)d_in[2];   // (1024,1024)
    const float* Wk = (const float*)d_in[3];
    const float* Wv = (const float*)d_in[4];
    float* out = (float*)d_out;                // (16,64,1024)

    __half *qh, *qth, *sch, *imgh, *audh, *wqh, *wkth, *wvh, *th;
    cudaGetSymbolAddress((void**)&qh, g_qh);
    cudaGetSymbolAddress((void**)&qth, g_qth);
    cudaGetSymbolAddress((void**)&sch, g_sch);
    cudaGetSymbolAddress((void**)&imgh, g_imgh);
    cudaGetSymbolAddress((void**)&audh, g_audh);
    cudaGetSymbolAddress((void**)&wqh, g_wqh);
    cudaGetSymbolAddress((void**)&wkth, g_wkth);
    cudaGetSymbolAddress((void**)&wvh, g_wvh);
    cudaGetSymbolAddress((void**)&th, g_th);

    cudaFuncSetAttribute(h16_gemm_kernel<true, true, false>,
                         cudaFuncAttributeMaxDynamicSharedMemorySize, SM_H16_NT);
    cudaFuncSetAttribute(h16_gemm_kernel<false, true, false>,
                         cudaFuncAttributeMaxDynamicSharedMemorySize, SM_H16_NN);
    cudaFuncSetAttribute(h16_gemm_kernel<true, true, true>,
                         cudaFuncAttributeMaxDynamicSharedMemorySize, SM_H16_NT);
    cudaFuncSetAttribute(h16_gemm_kernel<true, false, true>,
                         cudaFuncAttributeMaxDynamicSharedMemorySize, SM_H16_NT);

    const float scale = 0.08838834764831845f;  // (1024/8)^-0.5

    // 0) casts + Wk transpose
    cast_f2h_kernel<<<16384, 256>>>(img, imgh, 16 * 4096 * 1024 / 4);
    cast_f2h_kernel<<<1024, 256>>>(aud, audh, 16 * 64 * 1024 / 4);
    cast_f2h_kernel<<<1024, 256>>>(Wq, wqh, 1024 * 1024 / 4);
    cast_f2h_kernel<<<1024, 256>>>(Wv, wvh, 1024 * 1024 / 4);
    transpose_f2h_kernel<<<dim3(32, 32), 256>>>(Wk, wkth);

    // 1) qh = audh @ wqh^T : M=1024, N=1024, K=1024 (fp16 NT)
    h16_gemm_kernel<true, true, false><<<dim3(8, 8, 1), 256, SM_H16_NT>>>(
        audh, wqh, qh, 1024, 1024, 1024, 1024,
        0, 0, 0, 0, 0, 0, 1, 1.0f);

    // 2) qth[b,h] = Q_bh @ Wk_h : M=64(M64), N=1024, K=128; z=b*8+h
    h16_gemm_kernel<true, true, true><<<dim3(8, 1, 128), 256, SM_H16_NT>>>(
        qh, wkth, qth, 128, 1024, 1024, 1024,
        65536, 128, 0, 128, 524288, 65536, 8, 1.0f);

    // 3) sch_b = fp16(qt_b @ img_b^T * scale) : M=512, N=4096, K=1024 (NT)
    h16_gemm_kernel<true, true, false><<<dim3(32, 4, 16), 256, SM_H16_NT>>>(
        qth, imgh, sch, 1024, 1024, 1024, 4096,
        524288, 0, 4194304, 0, 2097152, 0, 1, scale);

    // 4) softmax rows, fp16 in-place (16*512 rows)
    softmax4096_h_kernel<<<16 * 512, 256>>>(sch);

    // 5) th_b = P_b @ img_b : M=512, N=1024, K=4096 (NN via ldmatrix.trans)
    h16_gemm_kernel<false, true, false><<<dim3(8, 4, 16), 256, SM_H16_NN>>>(
        sch, imgh, th, 4096, 4096, 1024, 1024,
        2097152, 0, 4194304, 0, 524288, 0, 1, 1.0f);

    // 6) out[b,:,hd:hd+128] = t_bh @ Wv_h^T : M=64(M64), N=128, K=1024; z=b*8+h
    h16_gemm_kernel<true, false, true><<<dim3(1, 1, 128), 256, SM_H16_NT>>>(
        th, wvh, out, 1024, 1024, 1024, 1024,
        524288, 65536, 0, 131072, 65536, 128, 8, 1.0f);
}